// round 10
// baseline (speedup 1.0000x reference)
#include <cuda_runtime.h>
#include <cuda_fp16.h>
#include <cstdint>
#include <math.h>

// Problem shape (fixed)
#define NB   4
#define SEQ  2048
#define DIN  1024
#define DH   1024

// ---------------------------------------------------------------------------
// Scratch (__device__ globals; no allocs allowed)
// ---------------------------------------------------------------------------
__device__ __half g_xh [(size_t)NB * SEQ * DIN];      // fp16 x            (16 MB)
__device__ __half g_Wqk[(size_t)2 * DH * DIN];        // [Wq; Wk] fp16     (4 MB)
__device__ __half g_Wv [(size_t)DH * DIN];            // fp16              (2 MB)
__device__ __half g_QK [(size_t)NB * SEQ * 2 * DH];   // [Q | K] fp16      (32 MB)
__device__ __half g_Vt [(size_t)NB * DH * SEQ];       // V^T fp16          (16 MB)
__device__ float  g_Sc [(size_t)NB * SEQ * SEQ];      // scores fp32       (64 MB)
__device__ __half g_At [(size_t)NB * SEQ * SEQ];      // attn fp16         (32 MB)

// ---------------------------------------------------------------------------
__device__ __forceinline__ uint32_t smem_u32(const void* p) {
    uint32_t a;
    asm("{ .reg .u64 t; cvta.to.shared.u64 t, %1; cvt.u32.u64 %0, t; }"
        : "=r"(a) : "l"(p));
    return a;
}

#define LDMATRIX_X4(r0, r1, r2, r3, addr)                                      \
    asm volatile("ldmatrix.sync.aligned.m8n8.x4.shared.b16 {%0,%1,%2,%3}, [%4];" \
                 : "=r"(r0), "=r"(r1), "=r"(r2), "=r"(r3) : "r"(addr))

// ---------------------------------------------------------------------------
// Shared mainloop: fp16 m16n8k16 NT GEMM body, C = alpha * A @ B^T
//   Tile 128x128x64, 8 warps (64x32 warp tile), 3-stage cp.async with
//   issuance spread across the ks loop, XOR swizzle, ldmatrix.x4.
// ---------------------------------------------------------------------------
constexpr int BM = 128, BN = 128, BK = 64, NST = 3;
constexpr int TILE_H  = BM * BK;                 // 8192 halfs = 16 KB per operand
constexpr int STAGE_H = 2 * TILE_H;              // 32 KB per stage
constexpr int SMEM_BYTES = NST * STAGE_H * 2;    // 98304 B

template <bool OUT_HALF>
__device__ __forceinline__
void gemm_body(const __half* __restrict__ Ab, const __half* __restrict__ Bb,
               void* __restrict__ Cb, int K,
               int ldA, int ldB, int ldC, float alpha,
               int bm, int bn, char* smraw)
{
    const int tid  = threadIdx.x;
    const int wid  = tid >> 5;
    const int lane = tid & 31;
    const int g    = lane >> 2;
    const int tig  = lane & 3;
    const int wm = wid >> 2;          // 0..1
    const int wn = wid & 3;           // 0..3
    const int KT = K / BK;

    const uint32_t smem_base = smem_u32(smraw);

    // ---- hoisted cp.async coordinates: 4 chunks, pointers advance by BK ----
    const __half* ga[4];
    const __half* gb[4];
    uint32_t so[4];
    #pragma unroll
    for (int i = 0; i < 4; i++) {
        const int idx = i * 256 + tid;
        const int row = idx >> 3;
        const int seg = idx & 7;
        so[i] = (uint32_t)(row * 128 + ((seg ^ (row & 7)) << 4));
        ga[i] = Ab + (size_t)(bm + row) * ldA + seg * 8;
        gb[i] = Bb + (size_t)(bn + row) * ldB + seg * 8;
    }

#define LOAD_CHUNK(bufbase, i) do {                                            \
        asm volatile("cp.async.cg.shared.global [%0], [%1], 16;"               \
                     :: "r"((bufbase) + so[i]), "l"(ga[i]));                   \
        asm volatile("cp.async.cg.shared.global [%0], [%1], 16;"               \
                     :: "r"((bufbase) + (uint32_t)(TILE_H * 2) + so[i]),       \
                        "l"(gb[i]));                                           \
        ga[i] += BK; gb[i] += BK;                                              \
    } while (0)

    // ldmatrix per-lane precompute
    const int xorv = lane & 7;
    const int rowA = wm * 64 + (lane & 7) + ((lane >> 3) & 1) * 8;
    const int selA = lane >> 4;
    const int rowB = wn * 32 + (lane & 7) + ((lane >> 4) & 1) * 8;
    const int selB = (lane >> 3) & 1;

    float acc[4][4][4];
    #pragma unroll
    for (int i = 0; i < 4; i++)
        #pragma unroll
        for (int j = 0; j < 4; j++)
            #pragma unroll
            for (int r = 0; r < 4; r++) acc[i][j][r] = 0.0f;

    // prologue: stages 0, 1
    {
        const uint32_t b0 = smem_base;
        const uint32_t b1 = smem_base + (uint32_t)(STAGE_H * 2);
        LOAD_CHUNK(b0, 0); LOAD_CHUNK(b0, 1); LOAD_CHUNK(b0, 2); LOAD_CHUNK(b0, 3);
        asm volatile("cp.async.commit_group;" ::: "memory");
        LOAD_CHUNK(b1, 0); LOAD_CHUNK(b1, 1); LOAD_CHUNK(b1, 2); LOAD_CHUNK(b1, 3);
        asm volatile("cp.async.commit_group;" ::: "memory");
    }

    int bufR = 0;                       // stage k0 buffer index
    int bufW = 2;                       // stage k0+2 buffer index

    for (int k0 = 0; k0 < KT; k0++) {
        if (k0 + 1 < KT) asm volatile("cp.async.wait_group 1;" ::: "memory");
        else             asm volatile("cp.async.wait_group 0;" ::: "memory");
        __syncthreads();

        const bool doLoad = (k0 + 2 < KT);
        const uint32_t stA = smem_base + (uint32_t)(bufR * STAGE_H * 2);
        const uint32_t stB = stA + (uint32_t)(TILE_H * 2);
        const uint32_t wBase = smem_base + (uint32_t)(bufW * STAGE_H * 2);
        const uint32_t aRowAddr = stA + (uint32_t)(rowA * 128);
        const uint32_t bRowAddr = stB + (uint32_t)(rowB * 128);

        #pragma unroll
        for (int ks = 0; ks < BK / 16; ks++) {
            if (doLoad) {
                LOAD_CHUNK(wBase, ks);
                if (ks == 3)
                    asm volatile("cp.async.commit_group;" ::: "memory");
            }

            const uint32_t offA = (uint32_t)(((2 * ks + selA) ^ xorv) << 4);
            const uint32_t offB = (uint32_t)(((2 * ks + selB) ^ xorv) << 4);
            uint32_t a[4][4], b[4][2];
            #pragma unroll
            for (int p = 0; p < 2; p++)
                LDMATRIX_X4(b[2 * p][0], b[2 * p][1], b[2 * p + 1][0], b[2 * p + 1][1],
                            bRowAddr + (uint32_t)(p * 16 * 128) + offB);
            #pragma unroll
            for (int mf = 0; mf < 4; mf++)
                LDMATRIX_X4(a[mf][0], a[mf][1], a[mf][2], a[mf][3],
                            aRowAddr + (uint32_t)(mf * 16 * 128) + offA);
            #pragma unroll
            for (int mf = 0; mf < 4; mf++)
                #pragma unroll
                for (int nf = 0; nf < 4; nf++)
                    asm volatile(
                        "mma.sync.aligned.m16n8k16.row.col.f32.f16.f16.f32 "
                        "{%0,%1,%2,%3}, {%4,%5,%6,%7}, {%8,%9}, {%0,%1,%2,%3};"
                        : "+f"(acc[mf][nf][0]), "+f"(acc[mf][nf][1]),
                          "+f"(acc[mf][nf][2]), "+f"(acc[mf][nf][3])
                        : "r"(a[mf][0]), "r"(a[mf][1]), "r"(a[mf][2]), "r"(a[mf][3]),
                          "r"(b[nf][0]), "r"(b[nf][1]));
        }

        bufR = (bufR == NST - 1) ? 0 : bufR + 1;
        bufW = (bufW == NST - 1) ? 0 : bufW + 1;
    }
#undef LOAD_CHUNK

    // Epilogue
    const int mBase = bm + wm * 64 + g;
    const int nBase = bn + wn * 32 + 2 * tig;
    #pragma unroll
    for (int mf = 0; mf < 4; mf++) {
        #pragma unroll
        for (int nf = 0; nf < 4; nf++) {
            const float v0 = acc[mf][nf][0] * alpha, v1 = acc[mf][nf][1] * alpha;
            const float v2 = acc[mf][nf][2] * alpha, v3 = acc[mf][nf][3] * alpha;
            const size_t r0 = (size_t)(mBase + mf * 16) * ldC + nBase + nf * 8;
            const size_t r1 = r0 + 8 * (size_t)ldC;
            if (OUT_HALF) {
                __half* Ch = (__half*)Cb;
                *reinterpret_cast<__half2*>(&Ch[r0]) =
                    __float22half2_rn(make_float2(v0, v1));
                *reinterpret_cast<__half2*>(&Ch[r1]) =
                    __float22half2_rn(make_float2(v2, v3));
            } else {
                float* Cf = (float*)Cb;
                *reinterpret_cast<float2*>(&Cf[r0]) = make_float2(v0, v1);
                *reinterpret_cast<float2*>(&Cf[r1]) = make_float2(v2, v3);
            }
        }
    }
}

// ---------------------------------------------------------------------------
// Generic batched NT GEMM kernel (used for scores and PV).
// ---------------------------------------------------------------------------
template <bool OUT_HALF>
__global__ __launch_bounds__(256, 2)
void gemm_h16_nt(const __half* __restrict__ A, const __half* __restrict__ B,
                 void* __restrict__ Cv, int K,
                 int ldA, int ldB, int ldC, float alpha,
                 size_t sA, size_t sB, size_t sC)
{
    extern __shared__ __align__(16) char smraw[];
    const __half* Ab = A + sA * blockIdx.z;
    const __half* Bb = B + sB * blockIdx.z;
    char* Cb = (char*)Cv + (OUT_HALF ? 2 : 4) * sC * blockIdx.z;
    gemm_body<OUT_HALF>(Ab, Bb, Cb, K, ldA, ldB, ldC, alpha,
                        blockIdx.y * BM, blockIdx.x * BN, smraw);
}

// ---------------------------------------------------------------------------
// Fused projection kernel: one launch does BOTH
//   blocks [0, 1024):   [Q|K] = xh @ wqk^T   (grid 16 x 64)
//   blocks [1024, 1536): V^T_b = wv @ xh_b^T (grid 16 x 8 per batch, 4 batches)
// ---------------------------------------------------------------------------
__global__ __launch_bounds__(256, 2)
void proj_all(const __half* __restrict__ xh, const __half* __restrict__ wqk,
              const __half* __restrict__ wv,
              __half* __restrict__ QK, __half* __restrict__ Vt)
{
    extern __shared__ __align__(16) char smraw[];
    const int bid = blockIdx.x;
    if (bid < 1024) {
        const int bx = bid & 15, by = bid >> 4;
        gemm_body<true>(xh, wqk, QK, DIN, DIN, DIN, 2 * DH, 1.0f,
                        by * BM, bx * BN, smraw);
    } else {
        const int t = bid - 1024;
        const int batch = t >> 7;           // 128 blocks per batch
        const int rest  = t & 127;
        const int bx = rest & 15, by = rest >> 4;   // N=SEQ (16), M=DH (8)
        gemm_body<true>(wv, xh + (size_t)batch * SEQ * DIN,
                        Vt + (size_t)batch * DH * SEQ,
                        DIN, DIN, DIN, SEQ, 1.0f,
                        by * BM, bx * BN, smraw);
    }
}

// ---------------------------------------------------------------------------
// Fused fp32 -> fp16 convert for x, Wq, Wk, Wv in ONE launch.
// ---------------------------------------------------------------------------
__global__ __launch_bounds__(256)
void cvt_all_kernel(const float4* __restrict__ x,  uint4* __restrict__ xh,
                    const float4* __restrict__ wq, const float4* __restrict__ wk,
                    uint4* __restrict__ wqk,
                    const float4* __restrict__ wv, uint4* __restrict__ wvh)
{
    const int b = blockIdx.x;
    const float4* src;
    uint4* dst;
    int off;
    if (b < 4096)      { src = x;  dst = xh;  off = b; }
    else if (b < 4608) { src = wq; dst = wqk; off = b - 4096; }
    else if (b < 5120) { src = wk; dst = wqk + (size_t)(DH * DIN) / 8; off = b - 4608; }
    else               { src = wv; dst = wvh; off = b - 5120; }

    const int i = off * 256 + threadIdx.x;
    const float4 u = src[2 * i], v = src[2 * i + 1];
    __half2 h0 = __float22half2_rn(make_float2(u.x, u.y));
    __half2 h1 = __float22half2_rn(make_float2(u.z, u.w));
    __half2 h2 = __float22half2_rn(make_float2(v.x, v.y));
    __half2 h3 = __float22half2_rn(make_float2(v.z, v.w));
    uint4 o;
    o.x = *reinterpret_cast<uint32_t*>(&h0);
    o.y = *reinterpret_cast<uint32_t*>(&h1);
    o.z = *reinterpret_cast<uint32_t*>(&h2);
    o.w = *reinterpret_cast<uint32_t*>(&h3);
    dst[i] = o;
}

// ---------------------------------------------------------------------------
// Row softmax: read fp32 scores, write fp16 attn.
// ---------------------------------------------------------------------------
__global__ __launch_bounds__(256)
void softmax_kernel(const float* __restrict__ S, __half* __restrict__ P)
{
    const float* row = S + (size_t)blockIdx.x * SEQ;
    __half*     orow = P + (size_t)blockIdx.x * SEQ;
    const int tid  = threadIdx.x;
    const int lane = tid & 31;
    const int warp = tid >> 5;

    float4 v0 = reinterpret_cast<const float4*>(row)[2 * tid];
    float4 v1 = reinterpret_cast<const float4*>(row)[2 * tid + 1];

    __shared__ float red[8];

    float m = fmaxf(fmaxf(fmaxf(v0.x, v0.y), fmaxf(v0.z, v0.w)),
                    fmaxf(fmaxf(v1.x, v1.y), fmaxf(v1.z, v1.w)));
    #pragma unroll
    for (int o = 16; o > 0; o >>= 1) m = fmaxf(m, __shfl_xor_sync(0xFFFFFFFFu, m, o));
    if (lane == 0) red[warp] = m;
    __syncthreads();
    m = red[0];
    #pragma unroll
    for (int w = 1; w < 8; w++) m = fmaxf(m, red[w]);
    __syncthreads();

    v0.x = __expf(v0.x - m); v0.y = __expf(v0.y - m);
    v0.z = __expf(v0.z - m); v0.w = __expf(v0.w - m);
    v1.x = __expf(v1.x - m); v1.y = __expf(v1.y - m);
    v1.z = __expf(v1.z - m); v1.w = __expf(v1.w - m);

    float s = (v0.x + v0.y + v0.z + v0.w) + (v1.x + v1.y + v1.z + v1.w);
    #pragma unroll
    for (int o = 16; o > 0; o >>= 1) s += __shfl_xor_sync(0xFFFFFFFFu, s, o);
    if (lane == 0) red[warp] = s;
    __syncthreads();
    s = red[0];
    #pragma unroll
    for (int w = 1; w < 8; w++) s += red[w];

    const float inv = 1.0f / s;
    __half2 h0 = __float22half2_rn(make_float2(v0.x * inv, v0.y * inv));
    __half2 h1 = __float22half2_rn(make_float2(v0.z * inv, v0.w * inv));
    __half2 h2 = __float22half2_rn(make_float2(v1.x * inv, v1.y * inv));
    __half2 h3 = __float22half2_rn(make_float2(v1.z * inv, v1.w * inv));
    uint4 o;
    o.x = *reinterpret_cast<uint32_t*>(&h0);
    o.y = *reinterpret_cast<uint32_t*>(&h1);
    o.z = *reinterpret_cast<uint32_t*>(&h2);
    o.w = *reinterpret_cast<uint32_t*>(&h3);
    reinterpret_cast<uint4*>(orow)[tid] = o;
}

// ---------------------------------------------------------------------------
extern "C" void kernel_launch(void* const* d_in, const int* in_sizes, int n_in,
                              void* d_out, int out_size)
{
    (void)in_sizes; (void)n_in; (void)out_size;

    const float* x  = (const float*)d_in[0];
    const float* Wq = (const float*)d_in[1];
    const float* Wk = (const float*)d_in[2];
    const float* Wv = (const float*)d_in[3];
    float*       out = (float*)d_out;

    __half *xh, *wqk, *wv, *QK, *Vt, *At;
    float *Sc;
    cudaGetSymbolAddress((void**)&xh,  g_xh);
    cudaGetSymbolAddress((void**)&wqk, g_Wqk);
    cudaGetSymbolAddress((void**)&wv,  g_Wv);
    cudaGetSymbolAddress((void**)&QK,  g_QK);
    cudaGetSymbolAddress((void**)&Vt,  g_Vt);
    cudaGetSymbolAddress((void**)&Sc,  g_Sc);
    cudaGetSymbolAddress((void**)&At,  g_At);

    cudaFuncSetAttribute(proj_all,
                         cudaFuncAttributeMaxDynamicSharedMemorySize, SMEM_BYTES);
    cudaFuncSetAttribute(gemm_h16_nt<false>,
                         cudaFuncAttributeMaxDynamicSharedMemorySize, SMEM_BYTES);

    // 0) convert all inputs to fp16, one launch
    cvt_all_kernel<<<5632, 256>>>((const float4*)x,  (uint4*)xh,
                                  (const float4*)Wq, (const float4*)Wk,
                                  (uint4*)wqk,
                                  (const float4*)Wv, (uint4*)wv);

    // 1) all projections ([Q|K] and V^T), one launch
    proj_all<<<1536, 256, SMEM_BYTES>>>(xh, wqk, wv, QK, Vt);

    // 2) scores_b = (Q_b @ K_b^T) / sqrt(SEQ), fp32 out
    {
        const float scale = 1.0f / sqrtf((float)SEQ);
        dim3 grid(SEQ / BN, SEQ / BM, NB);                // (16, 16, 4)
        gemm_h16_nt<false><<<grid, 256, SMEM_BYTES>>>(QK, QK + DH, Sc, DH,
                                                      2 * DH, 2 * DH, SEQ, scale,
                                                      (size_t)SEQ * 2 * DH,
                                                      (size_t)SEQ * 2 * DH,
                                                      (size_t)SEQ * SEQ);
    }

    // 3) softmax: fp32 scores -> fp16 attn
    softmax_kernel<<<NB * SEQ, 256>>>(Sc, At);

    // 4) out_b = attn_b @ (V^T_b)^T : M=SEQ, N=DH, K=SEQ, fp32 out
    {
        dim3 grid(DH / BN, SEQ / BM, NB);                 // (8, 16, 4)
        gemm_h16_nt<false><<<grid, 256, SMEM_BYTES>>>(At, Vt, out, SEQ,
                                                      SEQ, SEQ, DH, 1.0f,
                                                      (size_t)SEQ * SEQ,
                                                      (size_t)DH * SEQ,
                                                      (size_t)SEQ * DH);
    }
}

// round 11
// speedup vs baseline: 1.0419x; 1.0419x over previous
#include <cuda_runtime.h>
#include <cuda_fp16.h>
#include <cstdint>
#include <math.h>

// Problem shape (fixed)
#define NB   4
#define SEQ  2048
#define DIN  1024
#define DH   1024

// ---------------------------------------------------------------------------
// Scratch (__device__ globals; no allocs allowed)
// ---------------------------------------------------------------------------
__device__ __half g_xh [(size_t)NB * SEQ * DIN];      // fp16 x            (16 MB)
__device__ __half g_Wqk[(size_t)2 * DH * DIN];        // [Wq; Wk] fp16     (4 MB)
__device__ __half g_Wv [(size_t)DH * DIN];            // fp16              (2 MB)
__device__ __half g_QK [(size_t)NB * SEQ * 2 * DH];   // [Q | K] fp16      (32 MB)
__device__ __half g_Vt [(size_t)NB * DH * SEQ];       // V^T fp16          (16 MB)
__device__ __half g_At [(size_t)NB * SEQ * SEQ];      // scores/attn fp16  (32 MB)

// ---------------------------------------------------------------------------
__device__ __forceinline__ uint32_t smem_u32(const void* p) {
    uint32_t a;
    asm("{ .reg .u64 t; cvta.to.shared.u64 t, %1; cvt.u32.u64 %0, t; }"
        : "=r"(a) : "l"(p));
    return a;
}

#define LDMATRIX_X4(r0, r1, r2, r3, addr)                                      \
    asm volatile("ldmatrix.sync.aligned.m8n8.x4.shared.b16 {%0,%1,%2,%3}, [%4];" \
                 : "=r"(r0), "=r"(r1), "=r"(r2), "=r"(r3) : "r"(addr))

// ---------------------------------------------------------------------------
// fp16 m16n8k16 NT GEMM:  C = alpha * A @ B^T
//   A:[M,K] ldA halfs, B:[N,K] ldB halfs (both K-contiguous), fp32 accum.
//   Tile 128x128x64, 8 warps (64x32 warp tile), 3-stage cp.async (issuance
//   spread across the ks loop), XOR swizzle, ldmatrix.x4.
//   OUT_HALF: C is __half else float.
// ---------------------------------------------------------------------------
constexpr int BM = 128, BN = 128, BK = 64, NST = 3;
constexpr int TILE_H  = BM * BK;                 // 8192 halfs = 16 KB per operand
constexpr int STAGE_H = 2 * TILE_H;              // 32 KB per stage
constexpr int SMEM_BYTES = NST * STAGE_H * 2;    // 98304 B

template <bool OUT_HALF>
__global__ __launch_bounds__(256, 2)
void gemm_h16_nt(const __half* __restrict__ A, const __half* __restrict__ B,
                 void* __restrict__ Cv, int K,
                 int ldA, int ldB, int ldC, float alpha,
                 size_t sA, size_t sB, size_t sC)
{
    extern __shared__ __align__(16) __half sm[];

    const int tid  = threadIdx.x;
    const int wid  = tid >> 5;
    const int lane = tid & 31;
    const int g    = lane >> 2;      // 0..7
    const int tig  = lane & 3;       // 0..3

    const int wm = wid >> 2;         // 0..1 : 64-row warp slab
    const int wn = wid & 3;          // 0..3 : 32-col warp slab

    const __half* Ab = A + sA * blockIdx.z;
    const __half* Bb = B + sB * blockIdx.z;
    const int bm = blockIdx.y * BM;
    const int bn = blockIdx.x * BN;
    const int KT = K / BK;

    const uint32_t smem_base = smem_u32(sm);

    // ldmatrix per-lane row/chunk precompute (row&7 == lane&7 for all bases).
    const int xorv = lane & 7;
    const int rowA = wm * 64 + (lane & 7) + ((lane >> 3) & 1) * 8;
    const int selA = lane >> 4;                   // 0:c0 1:c1
    const int rowB = wn * 32 + (lane & 7) + ((lane >> 4) & 1) * 8;
    const int selB = (lane >> 3) & 1;             // 0:c0 1:c1

    // One chunk of a stage load: A-row-group i and B-row-group i (i = 0..3).
    // Full stage = 4 chunks. Chunk c of row r -> physical chunk c ^ (r & 7).
#define LOAD_CHUNK(s, i) do {                                                  \
        const uint32_t _base = smem_base + (uint32_t)(((s) % NST) * STAGE_H * 2); \
        const uint32_t _bB   = _base + (uint32_t)(TILE_H * 2);                 \
        const int _idx = (i) * 256 + tid;                                      \
        const int _row = _idx >> 3;                                            \
        const int _seg = _idx & 7;                                             \
        const uint32_t _soff = (uint32_t)(_row * 128 +                         \
                               ((_seg ^ (_row & 7)) << 4));                    \
        const __half* _ga = Ab + (size_t)(bm + _row) * ldA + (s) * BK + _seg * 8; \
        const __half* _gb = Bb + (size_t)(bn + _row) * ldB + (s) * BK + _seg * 8; \
        asm volatile("cp.async.cg.shared.global [%0], [%1], 16;"               \
                     :: "r"(_base + _soff), "l"(_ga));                         \
        asm volatile("cp.async.cg.shared.global [%0], [%1], 16;"               \
                     :: "r"(_bB + _soff), "l"(_gb));                           \
    } while (0)

#define LOAD_STAGE(s) do {                                                     \
        LOAD_CHUNK(s, 0); LOAD_CHUNK(s, 1); LOAD_CHUNK(s, 2); LOAD_CHUNK(s, 3);\
        asm volatile("cp.async.commit_group;" ::: "memory");                   \
    } while (0)

    float acc[4][4][4];
    #pragma unroll
    for (int i = 0; i < 4; i++)
        #pragma unroll
        for (int j = 0; j < 4; j++)
            #pragma unroll
            for (int r = 0; r < 4; r++) acc[i][j][r] = 0.0f;

    LOAD_STAGE(0);
    LOAD_STAGE(1);

    for (int k0 = 0; k0 < KT; k0++) {
        if (k0 + 1 < KT) asm volatile("cp.async.wait_group 1;" ::: "memory");
        else             asm volatile("cp.async.wait_group 0;" ::: "memory");
        __syncthreads();

        const bool doLoad = (k0 + 2 < KT);
        const uint32_t stA = smem_base + (uint32_t)((k0 % NST) * STAGE_H * 2);
        const uint32_t stB = stA + (uint32_t)(TILE_H * 2);
        const uint32_t aRowAddr = stA + (uint32_t)(rowA * 128);
        const uint32_t bRowAddr = stB + (uint32_t)(rowB * 128);

        #pragma unroll
        for (int ks = 0; ks < BK / 16; ks++) {
            // spread next-stage global loads across the 4 ks iterations
            if (doLoad) {
                LOAD_CHUNK(k0 + 2, ks);
                if (ks == 3)
                    asm volatile("cp.async.commit_group;" ::: "memory");
            }

            const uint32_t offA = (uint32_t)(((2 * ks + selA) ^ xorv) << 4);
            const uint32_t offB = (uint32_t)(((2 * ks + selB) ^ xorv) << 4);
            uint32_t a[4][4], b[4][2];
            #pragma unroll
            for (int p = 0; p < 2; p++)
                LDMATRIX_X4(b[2 * p][0], b[2 * p][1], b[2 * p + 1][0], b[2 * p + 1][1],
                            bRowAddr + (uint32_t)(p * 16 * 128) + offB);
            #pragma unroll
            for (int mf = 0; mf < 4; mf++)
                LDMATRIX_X4(a[mf][0], a[mf][1], a[mf][2], a[mf][3],
                            aRowAddr + (uint32_t)(mf * 16 * 128) + offA);
            #pragma unroll
            for (int mf = 0; mf < 4; mf++)
                #pragma unroll
                for (int nf = 0; nf < 4; nf++)
                    asm volatile(
                        "mma.sync.aligned.m16n8k16.row.col.f32.f16.f16.f32 "
                        "{%0,%1,%2,%3}, {%4,%5,%6,%7}, {%8,%9}, {%0,%1,%2,%3};"
                        : "+f"(acc[mf][nf][0]), "+f"(acc[mf][nf][1]),
                          "+f"(acc[mf][nf][2]), "+f"(acc[mf][nf][3])
                        : "r"(a[mf][0]), "r"(a[mf][1]), "r"(a[mf][2]), "r"(a[mf][3]),
                          "r"(b[nf][0]), "r"(b[nf][1]));
        }
    }
#undef LOAD_STAGE
#undef LOAD_CHUNK

    // Epilogue: direct float2 / half2 stores.
    const int mBase = bm + wm * 64 + g;
    const int nBase = bn + wn * 32 + 2 * tig;
    #pragma unroll
    for (int mf = 0; mf < 4; mf++) {
        #pragma unroll
        for (int nf = 0; nf < 4; nf++) {
            const float v0 = acc[mf][nf][0] * alpha, v1 = acc[mf][nf][1] * alpha;
            const float v2 = acc[mf][nf][2] * alpha, v3 = acc[mf][nf][3] * alpha;
            const size_t r0 = (size_t)(mBase + mf * 16) * ldC + nBase + nf * 8;
            const size_t r1 = r0 + 8 * (size_t)ldC;
            if (OUT_HALF) {
                __half* Ch = (__half*)Cv + sC * blockIdx.z;
                *reinterpret_cast<__half2*>(&Ch[r0]) =
                    __float22half2_rn(make_float2(v0, v1));
                *reinterpret_cast<__half2*>(&Ch[r1]) =
                    __float22half2_rn(make_float2(v2, v3));
            } else {
                float* Cf = (float*)Cv + sC * blockIdx.z;
                *reinterpret_cast<float2*>(&Cf[r0]) = make_float2(v0, v1);
                *reinterpret_cast<float2*>(&Cf[r1]) = make_float2(v2, v3);
            }
        }
    }
}

// ---------------------------------------------------------------------------
// Fused fp32 -> fp16 convert for x, Wq, Wk, Wv in ONE launch.
// Block map: [0,4096) x ; [4096,4608) Wq ; [4608,5120) Wk ; [5120,5632) Wv.
// ---------------------------------------------------------------------------
__global__ __launch_bounds__(256)
void cvt_all_kernel(const float4* __restrict__ x,  uint4* __restrict__ xh,
                    const float4* __restrict__ wq, const float4* __restrict__ wk,
                    uint4* __restrict__ wqk,
                    const float4* __restrict__ wv, uint4* __restrict__ wvh)
{
    const int b = blockIdx.x;
    const float4* src;
    uint4* dst;
    int off;
    if (b < 4096)      { src = x;  dst = xh;  off = b; }
    else if (b < 4608) { src = wq; dst = wqk; off = b - 4096; }
    else if (b < 5120) { src = wk; dst = wqk + (size_t)(DH * DIN) / 8; off = b - 4608; }
    else               { src = wv; dst = wvh; off = b - 5120; }

    const int i = off * 256 + threadIdx.x;
    const float4 u = src[2 * i], v = src[2 * i + 1];
    __half2 h0 = __float22half2_rn(make_float2(u.x, u.y));
    __half2 h1 = __float22half2_rn(make_float2(u.z, u.w));
    __half2 h2 = __float22half2_rn(make_float2(v.x, v.y));
    __half2 h3 = __float22half2_rn(make_float2(v.z, v.w));
    uint4 o;
    o.x = *reinterpret_cast<uint32_t*>(&h0);
    o.y = *reinterpret_cast<uint32_t*>(&h1);
    o.z = *reinterpret_cast<uint32_t*>(&h2);
    o.w = *reinterpret_cast<uint32_t*>(&h3);
    dst[i] = o;
}

// ---------------------------------------------------------------------------
// In-place row softmax on fp16 scores (fp32 math). One block per row:
// 256 threads x 8 halfs (one uint4 each).
// ---------------------------------------------------------------------------
__global__ __launch_bounds__(256)
void softmax_kernel(__half* __restrict__ S)
{
    __half* row = S + (size_t)blockIdx.x * SEQ;
    const int tid  = threadIdx.x;
    const int lane = tid & 31;
    const int warp = tid >> 5;

    const uint4 pin = reinterpret_cast<const uint4*>(row)[tid];
    float2 f0 = __half22float2(*reinterpret_cast<const __half2*>(&pin.x));
    float2 f1 = __half22float2(*reinterpret_cast<const __half2*>(&pin.y));
    float2 f2 = __half22float2(*reinterpret_cast<const __half2*>(&pin.z));
    float2 f3 = __half22float2(*reinterpret_cast<const __half2*>(&pin.w));

    __shared__ float red[8];

    float m = fmaxf(fmaxf(fmaxf(f0.x, f0.y), fmaxf(f1.x, f1.y)),
                    fmaxf(fmaxf(f2.x, f2.y), fmaxf(f3.x, f3.y)));
    #pragma unroll
    for (int o = 16; o > 0; o >>= 1) m = fmaxf(m, __shfl_xor_sync(0xFFFFFFFFu, m, o));
    if (lane == 0) red[warp] = m;
    __syncthreads();
    m = red[0];
    #pragma unroll
    for (int w = 1; w < 8; w++) m = fmaxf(m, red[w]);
    __syncthreads();

    f0.x = __expf(f0.x - m); f0.y = __expf(f0.y - m);
    f1.x = __expf(f1.x - m); f1.y = __expf(f1.y - m);
    f2.x = __expf(f2.x - m); f2.y = __expf(f2.y - m);
    f3.x = __expf(f3.x - m); f3.y = __expf(f3.y - m);

    float s = (f0.x + f0.y + f1.x + f1.y) + (f2.x + f2.y + f3.x + f3.y);
    #pragma unroll
    for (int o = 16; o > 0; o >>= 1) s += __shfl_xor_sync(0xFFFFFFFFu, s, o);
    if (lane == 0) red[warp] = s;
    __syncthreads();
    s = red[0];
    #pragma unroll
    for (int w = 1; w < 8; w++) s += red[w];

    const float inv = 1.0f / s;
    __half2 h0 = __float22half2_rn(make_float2(f0.x * inv, f0.y * inv));
    __half2 h1 = __float22half2_rn(make_float2(f1.x * inv, f1.y * inv));
    __half2 h2 = __float22half2_rn(make_float2(f2.x * inv, f2.y * inv));
    __half2 h3 = __float22half2_rn(make_float2(f3.x * inv, f3.y * inv));
    uint4 o;
    o.x = *reinterpret_cast<uint32_t*>(&h0);
    o.y = *reinterpret_cast<uint32_t*>(&h1);
    o.z = *reinterpret_cast<uint32_t*>(&h2);
    o.w = *reinterpret_cast<uint32_t*>(&h3);
    reinterpret_cast<uint4*>(row)[tid] = o;
}

// ---------------------------------------------------------------------------
extern "C" void kernel_launch(void* const* d_in, const int* in_sizes, int n_in,
                              void* d_out, int out_size)
{
    (void)in_sizes; (void)n_in; (void)out_size;

    const float* x  = (const float*)d_in[0];
    const float* Wq = (const float*)d_in[1];
    const float* Wk = (const float*)d_in[2];
    const float* Wv = (const float*)d_in[3];
    float*       out = (float*)d_out;

    __half *xh, *wqk, *wv, *QK, *Vt, *At;
    cudaGetSymbolAddress((void**)&xh,  g_xh);
    cudaGetSymbolAddress((void**)&wqk, g_Wqk);
    cudaGetSymbolAddress((void**)&wv,  g_Wv);
    cudaGetSymbolAddress((void**)&QK,  g_QK);
    cudaGetSymbolAddress((void**)&Vt,  g_Vt);
    cudaGetSymbolAddress((void**)&At,  g_At);

    cudaFuncSetAttribute(gemm_h16_nt<true>,
                         cudaFuncAttributeMaxDynamicSharedMemorySize, SMEM_BYTES);
    cudaFuncSetAttribute(gemm_h16_nt<false>,
                         cudaFuncAttributeMaxDynamicSharedMemorySize, SMEM_BYTES);

    // 0) convert all inputs to fp16, one launch
    cvt_all_kernel<<<5632, 256>>>((const float4*)x,  (uint4*)xh,
                                  (const float4*)Wq, (const float4*)Wk,
                                  (uint4*)wqk,
                                  (const float4*)Wv, (uint4*)wv);

    // 1) [Q|K] = xh @ [Wq;Wk]^T : one GEMM, N = 2*DH, fp16 out
    {
        dim3 grid((2 * DH) / BN, (NB * SEQ) / BM, 1);     // (16, 64)
        gemm_h16_nt<true><<<grid, 256, SMEM_BYTES>>>(xh, wqk, QK, DIN,
                                                     DIN, DIN, 2 * DH, 1.0f,
                                                     0, 0, 0);
    }

    // 2) V^T_b = Wv @ x_b^T : M=DH, N=SEQ, K=DIN (per batch), fp16 out
    {
        dim3 grid(SEQ / BN, DH / BM, NB);                 // (16, 8, 4)
        gemm_h16_nt<true><<<grid, 256, SMEM_BYTES>>>(wv, xh, Vt, DIN,
                                                     DIN, DIN, SEQ, 1.0f,
                                                     0, (size_t)SEQ * DIN,
                                                     (size_t)DH * SEQ);
    }

    // 3) scores_b = (Q_b @ K_b^T) / sqrt(SEQ), fp16 out -> At
    {
        const float scale = 1.0f / sqrtf((float)SEQ);
        dim3 grid(SEQ / BN, SEQ / BM, NB);                // (16, 16, 4)
        gemm_h16_nt<true><<<grid, 256, SMEM_BYTES>>>(QK, QK + DH, At, DH,
                                                     2 * DH, 2 * DH, SEQ, scale,
                                                     (size_t)SEQ * 2 * DH,
                                                     (size_t)SEQ * 2 * DH,
                                                     (size_t)SEQ * SEQ);
    }

    // 4) softmax: fp16 scores -> fp16 attn, in place
    softmax_kernel<<<NB * SEQ, 256>>>(At);

    // 5) out_b = attn_b @ (V^T_b)^T : M=SEQ, N=DH, K=SEQ, fp32 out
    {
        dim3 grid(DH / BN, SEQ / BM, NB);                 // (8, 16, 4)
        gemm_h16_nt<false><<<grid, 256, SMEM_BYTES>>>(At, Vt, out, SEQ,
                                                      SEQ, SEQ, DH, 1.0f,
                                                      (size_t)SEQ * SEQ,
                                                      (size_t)DH * SEQ,
                                                      (size_t)SEQ * DH);
    }
}

// round 12
// speedup vs baseline: 1.0467x; 1.0046x over previous
#include <cuda_runtime.h>
#include <cuda_fp16.h>
#include <cstdint>
#include <math.h>

// Problem shape (fixed)
#define NB   4
#define SEQ  2048
#define DIN  1024
#define DH   1024

// ---------------------------------------------------------------------------
// Scratch (__device__ globals; no allocs allowed)
// ---------------------------------------------------------------------------
__device__ __half g_xh [(size_t)NB * SEQ * DIN];      // fp16 x            (16 MB)
__device__ __half g_Wqk[(size_t)2 * DH * DIN];        // [Wq; Wk] fp16     (4 MB)
__device__ __half g_Wv [(size_t)DH * DIN];            // fp16              (2 MB)
__device__ __half g_QK [(size_t)NB * SEQ * 2 * DH];   // [Q | K] fp16      (32 MB)
__device__ __half g_Vt [(size_t)NB * DH * SEQ];       // V^T fp16          (16 MB)
__device__ __half g_At [(size_t)NB * SEQ * SEQ];      // scores/attn fp16  (32 MB)

// ---------------------------------------------------------------------------
__device__ __forceinline__ uint32_t smem_u32(const void* p) {
    uint32_t a;
    asm("{ .reg .u64 t; cvta.to.shared.u64 t, %1; cvt.u32.u64 %0, t; }"
        : "=r"(a) : "l"(p));
    return a;
}

#define LDMATRIX_X4(r0, r1, r2, r3, addr)                                      \
    asm volatile("ldmatrix.sync.aligned.m8n8.x4.shared.b16 {%0,%1,%2,%3}, [%4];" \
                 : "=r"(r0), "=r"(r1), "=r"(r2), "=r"(r3) : "r"(addr))

// ---------------------------------------------------------------------------
// fp16 m16n8k16 NT GEMM body:  C = alpha * A @ B^T
//   A:[M,K] ldA halfs, B:[N,K] ldB halfs (both K-contiguous), fp32 accum.
//   Tile 128x128x64, 8 warps (64x32 warp tile), 3-stage cp.async (issuance
//   spread across the ks loop), XOR swizzle, ldmatrix.x4.
//   All C addressing 32-bit (C < 2^31 elements).
// ---------------------------------------------------------------------------
constexpr int BM = 128, BN = 128, BK = 64, NST = 3;
constexpr int TILE_H  = BM * BK;                 // 8192 halfs = 16 KB per operand
constexpr int STAGE_H = 2 * TILE_H;              // 32 KB per stage
constexpr int SMEM_BYTES = NST * STAGE_H * 2;    // 98304 B

template <bool OUT_HALF>
__device__ __forceinline__
void gemm_body(const __half* __restrict__ Ab, const __half* __restrict__ Bb,
               void* __restrict__ Cb, int K,
               int ldA, int ldB, int ldC, float alpha,
               int bm, int bn)
{
    extern __shared__ __align__(16) __half sm[];

    const int tid  = threadIdx.x;
    const int wid  = tid >> 5;
    const int lane = tid & 31;
    const int g    = lane >> 2;      // 0..7
    const int tig  = lane & 3;       // 0..3

    const int wm = wid >> 2;         // 0..1 : 64-row warp slab
    const int wn = wid & 3;          // 0..3 : 32-col warp slab
    const int KT = K / BK;

    const uint32_t smem_base = smem_u32(sm);

    // ldmatrix per-lane row/chunk precompute (row&7 == lane&7 for all bases).
    const int xorv = lane & 7;
    const int rowA = wm * 64 + (lane & 7) + ((lane >> 3) & 1) * 8;
    const int selA = lane >> 4;                   // 0:c0 1:c1
    const int rowB = wn * 32 + (lane & 7) + ((lane >> 4) & 1) * 8;
    const int selB = (lane >> 3) & 1;             // 0:c0 1:c1

    // One chunk of a stage load: A-row-group i and B-row-group i (i = 0..3).
    // Full stage = 4 chunks. Chunk c of row r -> physical chunk c ^ (r & 7).
#define LOAD_CHUNK(s, i) do {                                                  \
        const uint32_t _base = smem_base + (uint32_t)(((s) % NST) * STAGE_H * 2); \
        const uint32_t _bB   = _base + (uint32_t)(TILE_H * 2);                 \
        const int _idx = (i) * 256 + tid;                                      \
        const int _row = _idx >> 3;                                            \
        const int _seg = _idx & 7;                                             \
        const uint32_t _soff = (uint32_t)(_row * 128 +                         \
                               ((_seg ^ (_row & 7)) << 4));                    \
        const __half* _ga = Ab + (uint32_t)(bm + _row) * (uint32_t)ldA         \
                               + (uint32_t)((s) * BK + _seg * 8);              \
        const __half* _gb = Bb + (uint32_t)(bn + _row) * (uint32_t)ldB         \
                               + (uint32_t)((s) * BK + _seg * 8);              \
        asm volatile("cp.async.cg.shared.global [%0], [%1], 16;"               \
                     :: "r"(_base + _soff), "l"(_ga));                         \
        asm volatile("cp.async.cg.shared.global [%0], [%1], 16;"               \
                     :: "r"(_bB + _soff), "l"(_gb));                           \
    } while (0)

#define LOAD_STAGE(s) do {                                                     \
        LOAD_CHUNK(s, 0); LOAD_CHUNK(s, 1); LOAD_CHUNK(s, 2); LOAD_CHUNK(s, 3);\
        asm volatile("cp.async.commit_group;" ::: "memory");                   \
    } while (0)

    float acc[4][4][4];
    #pragma unroll
    for (int i = 0; i < 4; i++)
        #pragma unroll
        for (int j = 0; j < 4; j++)
            #pragma unroll
            for (int r = 0; r < 4; r++) acc[i][j][r] = 0.0f;

    LOAD_STAGE(0);
    LOAD_STAGE(1);

    for (int k0 = 0; k0 < KT; k0++) {
        if (k0 + 1 < KT) asm volatile("cp.async.wait_group 1;" ::: "memory");
        else             asm volatile("cp.async.wait_group 0;" ::: "memory");
        __syncthreads();

        const bool doLoad = (k0 + 2 < KT);
        const uint32_t stA = smem_base + (uint32_t)((k0 % NST) * STAGE_H * 2);
        const uint32_t stB = stA + (uint32_t)(TILE_H * 2);
        const uint32_t aRowAddr = stA + (uint32_t)(rowA * 128);
        const uint32_t bRowAddr = stB + (uint32_t)(rowB * 128);

        #pragma unroll
        for (int ks = 0; ks < BK / 16; ks++) {
            // spread next-stage global loads across the 4 ks iterations
            if (doLoad) {
                LOAD_CHUNK(k0 + 2, ks);
                if (ks == 3)
                    asm volatile("cp.async.commit_group;" ::: "memory");
            }

            const uint32_t offA = (uint32_t)(((2 * ks + selA) ^ xorv) << 4);
            const uint32_t offB = (uint32_t)(((2 * ks + selB) ^ xorv) << 4);
            uint32_t a[4][4], b[4][2];
            #pragma unroll
            for (int p = 0; p < 2; p++)
                LDMATRIX_X4(b[2 * p][0], b[2 * p][1], b[2 * p + 1][0], b[2 * p + 1][1],
                            bRowAddr + (uint32_t)(p * 16 * 128) + offB);
            #pragma unroll
            for (int mf = 0; mf < 4; mf++)
                LDMATRIX_X4(a[mf][0], a[mf][1], a[mf][2], a[mf][3],
                            aRowAddr + (uint32_t)(mf * 16 * 128) + offA);
            #pragma unroll
            for (int mf = 0; mf < 4; mf++)
                #pragma unroll
                for (int nf = 0; nf < 4; nf++)
                    asm volatile(
                        "mma.sync.aligned.m16n8k16.row.col.f32.f16.f16.f32 "
                        "{%0,%1,%2,%3}, {%4,%5,%6,%7}, {%8,%9}, {%0,%1,%2,%3};"
                        : "+f"(acc[mf][nf][0]), "+f"(acc[mf][nf][1]),
                          "+f"(acc[mf][nf][2]), "+f"(acc[mf][nf][3])
                        : "r"(a[mf][0]), "r"(a[mf][1]), "r"(a[mf][2]), "r"(a[mf][3]),
                          "r"(b[nf][0]), "r"(b[nf][1]));
        }
    }
#undef LOAD_STAGE
#undef LOAD_CHUNK

    // Epilogue: direct float2 / half2 stores, 32-bit addressing.
    const uint32_t mBase = (uint32_t)(bm + wm * 64 + g);
    const uint32_t nBase = (uint32_t)(bn + wn * 32 + 2 * tig);
    #pragma unroll
    for (int mf = 0; mf < 4; mf++) {
        #pragma unroll
        for (int nf = 0; nf < 4; nf++) {
            const float v0 = acc[mf][nf][0] * alpha, v1 = acc[mf][nf][1] * alpha;
            const float v2 = acc[mf][nf][2] * alpha, v3 = acc[mf][nf][3] * alpha;
            const uint32_t r0 = (mBase + mf * 16) * (uint32_t)ldC + nBase + nf * 8;
            const uint32_t r1 = r0 + 8 * (uint32_t)ldC;
            if (OUT_HALF) {
                __half* Ch = (__half*)Cb;
                *reinterpret_cast<__half2*>(&Ch[r0]) =
                    __float22half2_rn(make_float2(v0, v1));
                *reinterpret_cast<__half2*>(&Ch[r1]) =
                    __float22half2_rn(make_float2(v2, v3));
            } else {
                float* Cf = (float*)Cb;
                *reinterpret_cast<float2*>(&Cf[r0]) = make_float2(v0, v1);
                *reinterpret_cast<float2*>(&Cf[r1]) = make_float2(v2, v3);
            }
        }
    }
}

// ---------------------------------------------------------------------------
// Generic batched NT GEMM kernel. 32-bit element strides.
// ---------------------------------------------------------------------------
template <bool OUT_HALF>
__global__ __launch_bounds__(256, 2)
void gemm_h16_nt(const __half* __restrict__ A, const __half* __restrict__ B,
                 void* __restrict__ Cv, int K,
                 int ldA, int ldB, int ldC, float alpha,
                 uint32_t sA, uint32_t sB, uint32_t sC)
{
    const __half* Ab = A + (size_t)sA * blockIdx.z;
    const __half* Bb = B + (size_t)sB * blockIdx.z;
    void* Cb = (char*)Cv + (size_t)(OUT_HALF ? 2 : 4) * sC * blockIdx.z;
    gemm_body<OUT_HALF>(Ab, Bb, Cb, K, ldA, ldB, ldC, alpha,
                        blockIdx.y * BM, blockIdx.x * BN);
}

// ---------------------------------------------------------------------------
// Merged Vt + scores kernel. grid (16, 24, NB):
//   y in [0,8):   V^T_b tile  (M=DH: y*128, N=SEQ: x*128)
//   y in [8,24):  scores_b tile (M=SEQ: (y-8)*128, N=SEQ: x*128)
// Single gemm_body call with runtime-selected params (no code duplication).
// ---------------------------------------------------------------------------
__global__ __launch_bounds__(256, 2)
void vt_scores_kernel(const __half* __restrict__ xh,
                      const __half* __restrict__ wv,
                      const __half* __restrict__ QK,
                      __half* __restrict__ Vt, __half* __restrict__ At,
                      float scale)
{
    const uint32_t z = blockIdx.z;
    const __half* A;  const __half* B;  __half* C;
    int K, ldA, ldB, ldC, bm;
    float alpha;
    if (blockIdx.y < 8) {              // V^T_b = Wv @ x_b^T
        A = wv;
        B = xh + (size_t)z * (SEQ * DIN);
        C = Vt + (size_t)z * (DH * SEQ);
        K = DIN; ldA = DIN; ldB = DIN; ldC = SEQ;
        bm = blockIdx.y * BM;
        alpha = 1.0f;
    } else {                            // scores_b = (Q_b @ K_b^T) * scale
        A = QK + (size_t)z * (SEQ * 2 * DH);
        B = A + DH;
        C = At + (size_t)z * (SEQ * SEQ);
        K = DH; ldA = 2 * DH; ldB = 2 * DH; ldC = SEQ;
        bm = (blockIdx.y - 8) * BM;
        alpha = scale;
    }
    gemm_body<true>(A, B, C, K, ldA, ldB, ldC, alpha, bm, blockIdx.x * BN);
}

// ---------------------------------------------------------------------------
// Fused fp32 -> fp16 convert for x, Wq, Wk, Wv in ONE launch.
// Block map: [0,4096) x ; [4096,4608) Wq ; [4608,5120) Wk ; [5120,5632) Wv.
// ---------------------------------------------------------------------------
__global__ __launch_bounds__(256)
void cvt_all_kernel(const float4* __restrict__ x,  uint4* __restrict__ xh,
                    const float4* __restrict__ wq, const float4* __restrict__ wk,
                    uint4* __restrict__ wqk,
                    const float4* __restrict__ wv, uint4* __restrict__ wvh)
{
    const int b = blockIdx.x;
    const float4* src;
    uint4* dst;
    int off;
    if (b < 4096)      { src = x;  dst = xh;  off = b; }
    else if (b < 4608) { src = wq; dst = wqk; off = b - 4096; }
    else if (b < 5120) { src = wk; dst = wqk + (size_t)(DH * DIN) / 8; off = b - 4608; }
    else               { src = wv; dst = wvh; off = b - 5120; }

    const int i = off * 256 + threadIdx.x;
    const float4 u = src[2 * i], v = src[2 * i + 1];
    __half2 h0 = __float22half2_rn(make_float2(u.x, u.y));
    __half2 h1 = __float22half2_rn(make_float2(u.z, u.w));
    __half2 h2 = __float22half2_rn(make_float2(v.x, v.y));
    __half2 h3 = __float22half2_rn(make_float2(v.z, v.w));
    uint4 o;
    o.x = *reinterpret_cast<uint32_t*>(&h0);
    o.y = *reinterpret_cast<uint32_t*>(&h1);
    o.z = *reinterpret_cast<uint32_t*>(&h2);
    o.w = *reinterpret_cast<uint32_t*>(&h3);
    dst[i] = o;
}

// ---------------------------------------------------------------------------
// In-place row softmax on fp16 scores (fp32 math). One block per row:
// 256 threads x 8 halfs (one uint4 each).
// ---------------------------------------------------------------------------
__global__ __launch_bounds__(256)
void softmax_kernel(__half* __restrict__ S)
{
    __half* row = S + (size_t)blockIdx.x * SEQ;
    const int tid  = threadIdx.x;
    const int lane = tid & 31;
    const int warp = tid >> 5;

    const uint4 pin = reinterpret_cast<const uint4*>(row)[tid];
    float2 f0 = __half22float2(*reinterpret_cast<const __half2*>(&pin.x));
    float2 f1 = __half22float2(*reinterpret_cast<const __half2*>(&pin.y));
    float2 f2 = __half22float2(*reinterpret_cast<const __half2*>(&pin.z));
    float2 f3 = __half22float2(*reinterpret_cast<const __half2*>(&pin.w));

    __shared__ float red[8];

    float m = fmaxf(fmaxf(fmaxf(f0.x, f0.y), fmaxf(f1.x, f1.y)),
                    fmaxf(fmaxf(f2.x, f2.y), fmaxf(f3.x, f3.y)));
    #pragma unroll
    for (int o = 16; o > 0; o >>= 1) m = fmaxf(m, __shfl_xor_sync(0xFFFFFFFFu, m, o));
    if (lane == 0) red[warp] = m;
    __syncthreads();
    m = red[0];
    #pragma unroll
    for (int w = 1; w < 8; w++) m = fmaxf(m, red[w]);
    __syncthreads();

    f0.x = __expf(f0.x - m); f0.y = __expf(f0.y - m);
    f1.x = __expf(f1.x - m); f1.y = __expf(f1.y - m);
    f2.x = __expf(f2.x - m); f2.y = __expf(f2.y - m);
    f3.x = __expf(f3.x - m); f3.y = __expf(f3.y - m);

    float s = (f0.x + f0.y + f1.x + f1.y) + (f2.x + f2.y + f3.x + f3.y);
    #pragma unroll
    for (int o = 16; o > 0; o >>= 1) s += __shfl_xor_sync(0xFFFFFFFFu, s, o);
    if (lane == 0) red[warp] = s;
    __syncthreads();
    s = red[0];
    #pragma unroll
    for (int w = 1; w < 8; w++) s += red[w];

    const float inv = 1.0f / s;
    __half2 h0 = __float22half2_rn(make_float2(f0.x * inv, f0.y * inv));
    __half2 h1 = __float22half2_rn(make_float2(f1.x * inv, f1.y * inv));
    __half2 h2 = __float22half2_rn(make_float2(f2.x * inv, f2.y * inv));
    __half2 h3 = __float22half2_rn(make_float2(f3.x * inv, f3.y * inv));
    uint4 o;
    o.x = *reinterpret_cast<uint32_t*>(&h0);
    o.y = *reinterpret_cast<uint32_t*>(&h1);
    o.z = *reinterpret_cast<uint32_t*>(&h2);
    o.w = *reinterpret_cast<uint32_t*>(&h3);
    reinterpret_cast<uint4*>(row)[tid] = o;
}

// ---------------------------------------------------------------------------
extern "C" void kernel_launch(void* const* d_in, const int* in_sizes, int n_in,
                              void* d_out, int out_size)
{
    (void)in_sizes; (void)n_in; (void)out_size;

    const float* x  = (const float*)d_in[0];
    const float* Wq = (const float*)d_in[1];
    const float* Wk = (const float*)d_in[2];
    const float* Wv = (const float*)d_in[3];
    float*       out = (float*)d_out;

    __half *xh, *wqk, *wv, *QK, *Vt, *At;
    cudaGetSymbolAddress((void**)&xh,  g_xh);
    cudaGetSymbolAddress((void**)&wqk, g_Wqk);
    cudaGetSymbolAddress((void**)&wv,  g_Wv);
    cudaGetSymbolAddress((void**)&QK,  g_QK);
    cudaGetSymbolAddress((void**)&Vt,  g_Vt);
    cudaGetSymbolAddress((void**)&At,  g_At);

    cudaFuncSetAttribute(gemm_h16_nt<true>,
                         cudaFuncAttributeMaxDynamicSharedMemorySize, SMEM_BYTES);
    cudaFuncSetAttribute(gemm_h16_nt<false>,
                         cudaFuncAttributeMaxDynamicSharedMemorySize, SMEM_BYTES);
    cudaFuncSetAttribute(vt_scores_kernel,
                         cudaFuncAttributeMaxDynamicSharedMemorySize, SMEM_BYTES);

    // 0) convert all inputs to fp16, one launch
    cvt_all_kernel<<<5632, 256>>>((const float4*)x,  (uint4*)xh,
                                  (const float4*)Wq, (const float4*)Wk,
                                  (uint4*)wqk,
                                  (const float4*)Wv, (uint4*)wv);

    // 1) [Q|K] = xh @ [Wq;Wk]^T : one GEMM, N = 2*DH, fp16 out
    {
        dim3 grid((2 * DH) / BN, (NB * SEQ) / BM, 1);     // (16, 64)
        gemm_h16_nt<true><<<grid, 256, SMEM_BYTES>>>(xh, wqk, QK, DIN,
                                                     DIN, DIN, 2 * DH, 1.0f,
                                                     0, 0, 0);
    }

    // 2) V^T (per batch) AND scores (per batch), one merged launch
    {
        const float scale = 1.0f / sqrtf((float)SEQ);
        dim3 grid(16, 24, NB);                            // 1536 CTAs
        vt_scores_kernel<<<grid, 256, SMEM_BYTES>>>(xh, wv, QK, Vt, At, scale);
    }

    // 3) softmax: fp16 scores -> fp16 attn, in place
    softmax_kernel<<<NB * SEQ, 256>>>(At);

    // 4) out_b = attn_b @ (V^T_b)^T : M=SEQ, N=DH, K=SEQ, fp32 out
    {
        dim3 grid(DH / BN, SEQ / BM, NB);                 // (8, 16, 4)
        gemm_h16_nt<false><<<grid, 256, SMEM_BYTES>>>(At, Vt, out, SEQ,
                                                      SEQ, SEQ, DH, 1.0f,
                                                      (uint32_t)(SEQ * SEQ),
                                                      (uint32_t)(DH * SEQ),
                                                      (uint32_t)(SEQ * DH));
    }
}

// round 13
// speedup vs baseline: 1.0579x; 1.0107x over previous
#include <cuda_runtime.h>
#include <cuda_fp16.h>
#include <cstdint>
#include <math.h>

// Problem shape (fixed)
#define NB   4
#define SEQ  2048
#define DIN  1024
#define DH   1024

// ---------------------------------------------------------------------------
// Scratch (__device__ globals; no allocs allowed)
// ---------------------------------------------------------------------------
__device__ __half g_xh [(size_t)NB * SEQ * DIN];      // fp16 x            (16 MB)
__device__ __half g_Wqk[(size_t)2 * DH * DIN];        // [Wq; Wk] fp16     (4 MB)
__device__ __half g_Wv [(size_t)DH * DIN];            // fp16              (2 MB)
__device__ __half g_QK [(size_t)NB * SEQ * 2 * DH];   // [Q | K] fp16      (32 MB)
__device__ __half g_Vt [(size_t)NB * DH * SEQ];       // V^T fp16          (16 MB)
__device__ __half g_At [(size_t)NB * SEQ * SEQ];      // exp-scores fp16   (32 MB)
__device__ float  g_Inv[(size_t)NB * SEQ];            // 1/rowsum          (32 KB)

// ---------------------------------------------------------------------------
__device__ __forceinline__ uint32_t smem_u32(const void* p) {
    uint32_t a;
    asm("{ .reg .u64 t; cvta.to.shared.u64 t, %1; cvt.u32.u64 %0, t; }"
        : "=r"(a) : "l"(p));
    return a;
}

#define LDMATRIX_X4(r0, r1, r2, r3, addr)                                      \
    asm volatile("ldmatrix.sync.aligned.m8n8.x4.shared.b16 {%0,%1,%2,%3}, [%4];" \
                 : "=r"(r0), "=r"(r1), "=r"(r2), "=r"(r3) : "r"(addr))

// ---------------------------------------------------------------------------
// fp16 m16n8k16 NT GEMM body:  C = f(alpha * A @ B^T)
//   f = exp() if doExp; per-row scale by rowInv[] if non-null (fp32 out only).
//   Tile 128x128x64, 8 warps (64x32 warp tile), 3-stage cp.async (issuance
//   spread across the ks loop), XOR swizzle, ldmatrix.x4.
// ---------------------------------------------------------------------------
constexpr int BM = 128, BN = 128, BK = 64, NST = 3;
constexpr int TILE_H  = BM * BK;                 // 8192 halfs = 16 KB per operand
constexpr int STAGE_H = 2 * TILE_H;              // 32 KB per stage
constexpr int SMEM_BYTES = NST * STAGE_H * 2;    // 98304 B

template <bool OUT_HALF>
__device__ __forceinline__
void gemm_body(const __half* __restrict__ Ab, const __half* __restrict__ Bb,
               void* __restrict__ Cb, int K,
               int ldA, int ldB, int ldC, float alpha,
               int bm, int bn, int doExp, const float* __restrict__ rowInv)
{
    extern __shared__ __align__(16) __half sm[];

    const int tid  = threadIdx.x;
    const int wid  = tid >> 5;
    const int lane = tid & 31;
    const int g    = lane >> 2;      // 0..7
    const int tig  = lane & 3;       // 0..3

    const int wm = wid >> 2;         // 0..1 : 64-row warp slab
    const int wn = wid & 3;          // 0..3 : 32-col warp slab
    const int KT = K / BK;

    const uint32_t smem_base = smem_u32(sm);

    // ldmatrix per-lane row/chunk precompute (row&7 == lane&7 for all bases).
    const int xorv = lane & 7;
    const int rowA = wm * 64 + (lane & 7) + ((lane >> 3) & 1) * 8;
    const int selA = lane >> 4;                   // 0:c0 1:c1
    const int rowB = wn * 32 + (lane & 7) + ((lane >> 4) & 1) * 8;
    const int selB = (lane >> 3) & 1;             // 0:c0 1:c1

    // One chunk of a stage load: A-row-group i and B-row-group i (i = 0..3).
    // Full stage = 4 chunks. Chunk c of row r -> physical chunk c ^ (r & 7).
#define LOAD_CHUNK(s, i) do {                                                  \
        const uint32_t _base = smem_base + (uint32_t)(((s) % NST) * STAGE_H * 2); \
        const uint32_t _bB   = _base + (uint32_t)(TILE_H * 2);                 \
        const int _idx = (i) * 256 + tid;                                      \
        const int _row = _idx >> 3;                                            \
        const int _seg = _idx & 7;                                             \
        const uint32_t _soff = (uint32_t)(_row * 128 +                         \
                               ((_seg ^ (_row & 7)) << 4));                    \
        const __half* _ga = Ab + (uint32_t)(bm + _row) * (uint32_t)ldA         \
                               + (uint32_t)((s) * BK + _seg * 8);              \
        const __half* _gb = Bb + (uint32_t)(bn + _row) * (uint32_t)ldB         \
                               + (uint32_t)((s) * BK + _seg * 8);              \
        asm volatile("cp.async.cg.shared.global [%0], [%1], 16;"               \
                     :: "r"(_base + _soff), "l"(_ga));                         \
        asm volatile("cp.async.cg.shared.global [%0], [%1], 16;"               \
                     :: "r"(_bB + _soff), "l"(_gb));                           \
    } while (0)

#define LOAD_STAGE(s) do {                                                     \
        LOAD_CHUNK(s, 0); LOAD_CHUNK(s, 1); LOAD_CHUNK(s, 2); LOAD_CHUNK(s, 3);\
        asm volatile("cp.async.commit_group;" ::: "memory");                   \
    } while (0)

    float acc[4][4][4];
    #pragma unroll
    for (int i = 0; i < 4; i++)
        #pragma unroll
        for (int j = 0; j < 4; j++)
            #pragma unroll
            for (int r = 0; r < 4; r++) acc[i][j][r] = 0.0f;

    LOAD_STAGE(0);
    LOAD_STAGE(1);

    for (int k0 = 0; k0 < KT; k0++) {
        if (k0 + 1 < KT) asm volatile("cp.async.wait_group 1;" ::: "memory");
        else             asm volatile("cp.async.wait_group 0;" ::: "memory");
        __syncthreads();

        const bool doLoad = (k0 + 2 < KT);
        const uint32_t stA = smem_base + (uint32_t)((k0 % NST) * STAGE_H * 2);
        const uint32_t stB = stA + (uint32_t)(TILE_H * 2);
        const uint32_t aRowAddr = stA + (uint32_t)(rowA * 128);
        const uint32_t bRowAddr = stB + (uint32_t)(rowB * 128);

        #pragma unroll
        for (int ks = 0; ks < BK / 16; ks++) {
            // spread next-stage global loads across the 4 ks iterations
            if (doLoad) {
                LOAD_CHUNK(k0 + 2, ks);
                if (ks == 3)
                    asm volatile("cp.async.commit_group;" ::: "memory");
            }

            const uint32_t offA = (uint32_t)(((2 * ks + selA) ^ xorv) << 4);
            const uint32_t offB = (uint32_t)(((2 * ks + selB) ^ xorv) << 4);
            uint32_t a[4][4], b[4][2];
            #pragma unroll
            for (int p = 0; p < 2; p++)
                LDMATRIX_X4(b[2 * p][0], b[2 * p][1], b[2 * p + 1][0], b[2 * p + 1][1],
                            bRowAddr + (uint32_t)(p * 16 * 128) + offB);
            #pragma unroll
            for (int mf = 0; mf < 4; mf++)
                LDMATRIX_X4(a[mf][0], a[mf][1], a[mf][2], a[mf][3],
                            aRowAddr + (uint32_t)(mf * 16 * 128) + offA);
            #pragma unroll
            for (int mf = 0; mf < 4; mf++)
                #pragma unroll
                for (int nf = 0; nf < 4; nf++)
                    asm volatile(
                        "mma.sync.aligned.m16n8k16.row.col.f32.f16.f16.f32 "
                        "{%0,%1,%2,%3}, {%4,%5,%6,%7}, {%8,%9}, {%0,%1,%2,%3};"
                        : "+f"(acc[mf][nf][0]), "+f"(acc[mf][nf][1]),
                          "+f"(acc[mf][nf][2]), "+f"(acc[mf][nf][3])
                        : "r"(a[mf][0]), "r"(a[mf][1]), "r"(a[mf][2]), "r"(a[mf][3]),
                          "r"(b[nf][0]), "r"(b[nf][1]));
        }
    }
#undef LOAD_STAGE
#undef LOAD_CHUNK

    // Epilogue: optional exp(), optional per-row reciprocal scale.
    const uint32_t mBase = (uint32_t)(bm + wm * 64 + g);
    const uint32_t nBase = (uint32_t)(bn + wn * 32 + 2 * tig);
    #pragma unroll
    for (int mf = 0; mf < 4; mf++) {
        float ri0 = 1.0f, ri1 = 1.0f;
        if (!OUT_HALF && rowInv) {
            ri0 = rowInv[mBase + mf * 16];
            ri1 = rowInv[mBase + mf * 16 + 8];
        }
        #pragma unroll
        for (int nf = 0; nf < 4; nf++) {
            float v0 = acc[mf][nf][0] * alpha, v1 = acc[mf][nf][1] * alpha;
            float v2 = acc[mf][nf][2] * alpha, v3 = acc[mf][nf][3] * alpha;
            if (doExp) {
                v0 = __expf(v0); v1 = __expf(v1);
                v2 = __expf(v2); v3 = __expf(v3);
            }
            const uint32_t r0 = (mBase + mf * 16) * (uint32_t)ldC + nBase + nf * 8;
            const uint32_t r1 = r0 + 8 * (uint32_t)ldC;
            if (OUT_HALF) {
                __half* Ch = (__half*)Cb;
                *reinterpret_cast<__half2*>(&Ch[r0]) =
                    __float22half2_rn(make_float2(v0, v1));
                *reinterpret_cast<__half2*>(&Ch[r1]) =
                    __float22half2_rn(make_float2(v2, v3));
            } else {
                float* Cf = (float*)Cb;
                *reinterpret_cast<float2*>(&Cf[r0]) = make_float2(v0 * ri0, v1 * ri0);
                *reinterpret_cast<float2*>(&Cf[r1]) = make_float2(v2 * ri1, v3 * ri1);
            }
        }
    }
}

// ---------------------------------------------------------------------------
// Generic batched NT GEMM kernel. 32-bit element strides.
// rowInv (fp32-out only): per-row reciprocal scale, indexed within batch.
// ---------------------------------------------------------------------------
template <bool OUT_HALF>
__global__ __launch_bounds__(256, 2)
void gemm_h16_nt(const __half* __restrict__ A, const __half* __restrict__ B,
                 void* __restrict__ Cv, int K,
                 int ldA, int ldB, int ldC, float alpha,
                 uint32_t sA, uint32_t sB, uint32_t sC,
                 const float* __restrict__ rowInv, uint32_t sInv)
{
    const __half* Ab = A + (size_t)sA * blockIdx.z;
    const __half* Bb = B + (size_t)sB * blockIdx.z;
    void* Cb = (char*)Cv + (size_t)(OUT_HALF ? 2 : 4) * sC * blockIdx.z;
    const float* ri = rowInv ? rowInv + (size_t)sInv * blockIdx.z : nullptr;
    gemm_body<OUT_HALF>(Ab, Bb, Cb, K, ldA, ldB, ldC, alpha,
                        blockIdx.y * BM, blockIdx.x * BN, 0, ri);
}

// ---------------------------------------------------------------------------
// Merged Vt + exp-scores kernel. grid (16, 24, NB):
//   y in [0,8):   V^T_b tile  (M=DH: y*128, N=SEQ: x*128)
//   y in [8,24):  exp-scores tile: exp((Q_b @ K_b^T) * scale), fp16 -> At
// ---------------------------------------------------------------------------
__global__ __launch_bounds__(256, 2)
void vt_scores_kernel(const __half* __restrict__ xh,
                      const __half* __restrict__ wv,
                      const __half* __restrict__ QK,
                      __half* __restrict__ Vt, __half* __restrict__ At,
                      float scale)
{
    const uint32_t z = blockIdx.z;
    const __half* A;  const __half* B;  __half* C;
    int K, ldA, ldB, ldC, bm, doExp;
    float alpha;
    if (blockIdx.y < 8) {              // V^T_b = Wv @ x_b^T
        A = wv;
        B = xh + (size_t)z * (SEQ * DIN);
        C = Vt + (size_t)z * (DH * SEQ);
        K = DIN; ldA = DIN; ldB = DIN; ldC = SEQ;
        bm = blockIdx.y * BM;
        alpha = 1.0f; doExp = 0;
    } else {                            // exp-scores
        A = QK + (size_t)z * (SEQ * 2 * DH);
        B = A + DH;
        C = At + (size_t)z * (SEQ * SEQ);
        K = DH; ldA = 2 * DH; ldB = 2 * DH; ldC = SEQ;
        bm = (blockIdx.y - 8) * BM;
        alpha = scale; doExp = 1;
    }
    gemm_body<true>(A, B, C, K, ldA, ldB, ldC, alpha, bm, blockIdx.x * BN,
                    doExp, nullptr);
}

// ---------------------------------------------------------------------------
// Fused fp32 -> fp16 convert for x, Wq, Wk, Wv in ONE launch.
// Block map: [0,4096) x ; [4096,4608) Wq ; [4608,5120) Wk ; [5120,5632) Wv.
// ---------------------------------------------------------------------------
__global__ __launch_bounds__(256)
void cvt_all_kernel(const float4* __restrict__ x,  uint4* __restrict__ xh,
                    const float4* __restrict__ wq, const float4* __restrict__ wk,
                    uint4* __restrict__ wqk,
                    const float4* __restrict__ wv, uint4* __restrict__ wvh)
{
    const int b = blockIdx.x;
    const float4* src;
    uint4* dst;
    int off;
    if (b < 4096)      { src = x;  dst = xh;  off = b; }
    else if (b < 4608) { src = wq; dst = wqk; off = b - 4096; }
    else if (b < 5120) { src = wk; dst = wqk + (size_t)(DH * DIN) / 8; off = b - 4608; }
    else               { src = wv; dst = wvh; off = b - 5120; }

    const int i = off * 256 + threadIdx.x;
    const float4 u = src[2 * i], v = src[2 * i + 1];
    __half2 h0 = __float22half2_rn(make_float2(u.x, u.y));
    __half2 h1 = __float22half2_rn(make_float2(u.z, u.w));
    __half2 h2 = __float22half2_rn(make_float2(v.x, v.y));
    __half2 h3 = __float22half2_rn(make_float2(v.z, v.w));
    uint4 o;
    o.x = *reinterpret_cast<uint32_t*>(&h0);
    o.y = *reinterpret_cast<uint32_t*>(&h1);
    o.z = *reinterpret_cast<uint32_t*>(&h2);
    o.w = *reinterpret_cast<uint32_t*>(&h3);
    dst[i] = o;
}

// ---------------------------------------------------------------------------
// Row-sum of exp-scores -> reciprocal. One block per row; 256 thr x 8 halfs.
// ---------------------------------------------------------------------------
__global__ __launch_bounds__(256)
void rowsum_kernel(const __half* __restrict__ E, float* __restrict__ inv)
{
    const __half* row = E + (size_t)blockIdx.x * SEQ;
    const int tid  = threadIdx.x;
    const int lane = tid & 31;
    const int warp = tid >> 5;

    const uint4 pin = reinterpret_cast<const uint4*>(row)[tid];
    float2 f0 = __half22float2(*reinterpret_cast<const __half2*>(&pin.x));
    float2 f1 = __half22float2(*reinterpret_cast<const __half2*>(&pin.y));
    float2 f2 = __half22float2(*reinterpret_cast<const __half2*>(&pin.z));
    float2 f3 = __half22float2(*reinterpret_cast<const __half2*>(&pin.w));

    float s = (f0.x + f0.y + f1.x + f1.y) + (f2.x + f2.y + f3.x + f3.y);
    #pragma unroll
    for (int o = 16; o > 0; o >>= 1) s += __shfl_xor_sync(0xFFFFFFFFu, s, o);

    __shared__ float red[8];
    if (lane == 0) red[warp] = s;
    __syncthreads();
    if (tid == 0) {
        float t = red[0];
        #pragma unroll
        for (int w = 1; w < 8; w++) t += red[w];
        inv[blockIdx.x] = 1.0f / t;
    }
}

// ---------------------------------------------------------------------------
extern "C" void kernel_launch(void* const* d_in, const int* in_sizes, int n_in,
                              void* d_out, int out_size)
{
    (void)in_sizes; (void)n_in; (void)out_size;

    const float* x  = (const float*)d_in[0];
    const float* Wq = (const float*)d_in[1];
    const float* Wk = (const float*)d_in[2];
    const float* Wv = (const float*)d_in[3];
    float*       out = (float*)d_out;

    __half *xh, *wqk, *wv, *QK, *Vt, *At;
    float *inv;
    cudaGetSymbolAddress((void**)&xh,  g_xh);
    cudaGetSymbolAddress((void**)&wqk, g_Wqk);
    cudaGetSymbolAddress((void**)&wv,  g_Wv);
    cudaGetSymbolAddress((void**)&QK,  g_QK);
    cudaGetSymbolAddress((void**)&Vt,  g_Vt);
    cudaGetSymbolAddress((void**)&At,  g_At);
    cudaGetSymbolAddress((void**)&inv, g_Inv);

    cudaFuncSetAttribute(gemm_h16_nt<true>,
                         cudaFuncAttributeMaxDynamicSharedMemorySize, SMEM_BYTES);
    cudaFuncSetAttribute(gemm_h16_nt<false>,
                         cudaFuncAttributeMaxDynamicSharedMemorySize, SMEM_BYTES);
    cudaFuncSetAttribute(vt_scores_kernel,
                         cudaFuncAttributeMaxDynamicSharedMemorySize, SMEM_BYTES);

    // 0) convert all inputs to fp16, one launch
    cvt_all_kernel<<<5632, 256>>>((const float4*)x,  (uint4*)xh,
                                  (const float4*)Wq, (const float4*)Wk,
                                  (uint4*)wqk,
                                  (const float4*)Wv, (uint4*)wv);

    // 1) [Q|K] = xh @ [Wq;Wk]^T : one GEMM, N = 2*DH, fp16 out
    {
        dim3 grid((2 * DH) / BN, (NB * SEQ) / BM, 1);     // (16, 64)
        gemm_h16_nt<true><<<grid, 256, SMEM_BYTES>>>(xh, wqk, QK, DIN,
                                                     DIN, DIN, 2 * DH, 1.0f,
                                                     0, 0, 0, nullptr, 0);
    }

    // 2) V^T (per batch) AND exp-scores (per batch), one merged launch
    {
        const float scale = 1.0f / sqrtf((float)SEQ);
        dim3 grid(16, 24, NB);                            // 1536 CTAs
        vt_scores_kernel<<<grid, 256, SMEM_BYTES>>>(xh, wv, QK, Vt, At, scale);
    }

    // 3) row sums of exp-scores -> reciprocals
    rowsum_kernel<<<NB * SEQ, 256>>>(At, inv);

    // 4) out_b = (expS_b @ (V^T_b)^T) * inv[row] : M=SEQ, N=DH, K=SEQ, fp32 out
    {
        dim3 grid(DH / BN, SEQ / BM, NB);                 // (8, 16, 4)
        gemm_h16_nt<false><<<grid, 256, SMEM_BYTES>>>(At, Vt, out, SEQ,
                                                      SEQ, SEQ, DH, 1.0f,
                                                      (uint32_t)(SEQ * SEQ),
                                                      (uint32_t)(DH * SEQ),
                                                      (uint32_t)(SEQ * DH),
                                                      inv, (uint32_t)SEQ);
    }
}

// round 14
// speedup vs baseline: 1.0801x; 1.0209x over previous
#include <cuda_runtime.h>
#include <cuda_fp16.h>
#include <cstdint>
#include <math.h>

// Problem shape (fixed)
#define NB   4
#define SEQ  2048
#define DIN  1024
#define DH   1024

// ---------------------------------------------------------------------------
// Scratch (__device__ globals; no allocs allowed)
// ---------------------------------------------------------------------------
__device__ __half g_xh [(size_t)NB * SEQ * DIN];      // fp16 x            (16 MB)
__device__ __half g_Wqk[(size_t)2 * DH * DIN];        // [Wq; Wk] fp16     (4 MB)
__device__ __half g_Wv [(size_t)DH * DIN];            // fp16              (2 MB)
__device__ __half g_QK [(size_t)NB * SEQ * 2 * DH];   // [Q | K] fp16      (32 MB)
__device__ __half g_Vt [(size_t)NB * DH * SEQ];       // V^T fp16          (16 MB)
__device__ __half g_At [(size_t)NB * SEQ * SEQ];      // exp-scores fp16   (32 MB)
__device__ float  g_Part[(size_t)16 * NB * SEQ];      // row partials      (512 KB)
__device__ float  g_Inv[(size_t)NB * SEQ];            // 1/rowsum          (32 KB)

// ---------------------------------------------------------------------------
__device__ __forceinline__ uint32_t smem_u32(const void* p) {
    uint32_t a;
    asm("{ .reg .u64 t; cvta.to.shared.u64 t, %1; cvt.u32.u64 %0, t; }"
        : "=r"(a) : "l"(p));
    return a;
}

#define LDMATRIX_X4(r0, r1, r2, r3, addr)                                      \
    asm volatile("ldmatrix.sync.aligned.m8n8.x4.shared.b16 {%0,%1,%2,%3}, [%4];" \
                 : "=r"(r0), "=r"(r1), "=r"(r2), "=r"(r3) : "r"(addr))

// ---------------------------------------------------------------------------
// fp16 m16n8k16 NT GEMM body:  C = f(alpha * A @ B^T)
//   doExp: apply exp() in epilogue; if partBase != nullptr also emit per-row
//   partial sums (128 floats, coalesced) for deferred softmax normalization.
//   rowInv (fp32 out only): per-row reciprocal scale.
//   Tile 128x128x64, 8 warps (64x32 warp tile), 3-stage cp.async, XOR swizzle.
// ---------------------------------------------------------------------------
constexpr int BM = 128, BN = 128, BK = 64, NST = 3;
constexpr int TILE_H  = BM * BK;                 // 8192 halfs = 16 KB per operand
constexpr int STAGE_H = 2 * TILE_H;              // 32 KB per stage
constexpr int SMEM_BYTES = NST * STAGE_H * 2;    // 98304 B

template <bool OUT_HALF>
__device__ __forceinline__
void gemm_body(const __half* __restrict__ Ab, const __half* __restrict__ Bb,
               void* __restrict__ Cb, int K,
               int ldA, int ldB, int ldC, float alpha,
               int bm, int bn, int doExp,
               const float* __restrict__ rowInv,
               float* __restrict__ partBase)
{
    extern __shared__ __align__(16) __half sm[];

    const int tid  = threadIdx.x;
    const int wid  = tid >> 5;
    const int lane = tid & 31;
    const int g    = lane >> 2;      // 0..7
    const int tig  = lane & 3;       // 0..3

    const int wm = wid >> 2;         // 0..1 : 64-row warp slab
    const int wn = wid & 3;          // 0..3 : 32-col warp slab
    const int KT = K / BK;

    const uint32_t smem_base = smem_u32(sm);

    // ldmatrix per-lane row/chunk precompute (row&7 == lane&7 for all bases).
    const int xorv = lane & 7;
    const int rowA = wm * 64 + (lane & 7) + ((lane >> 3) & 1) * 8;
    const int selA = lane >> 4;                   // 0:c0 1:c1
    const int rowB = wn * 32 + (lane & 7) + ((lane >> 4) & 1) * 8;
    const int selB = (lane >> 3) & 1;             // 0:c0 1:c1

#define LOAD_CHUNK(s, i) do {                                                  \
        const uint32_t _base = smem_base + (uint32_t)(((s) % NST) * STAGE_H * 2); \
        const uint32_t _bB   = _base + (uint32_t)(TILE_H * 2);                 \
        const int _idx = (i) * 256 + tid;                                      \
        const int _row = _idx >> 3;                                            \
        const int _seg = _idx & 7;                                             \
        const uint32_t _soff = (uint32_t)(_row * 128 +                         \
                               ((_seg ^ (_row & 7)) << 4));                    \
        const __half* _ga = Ab + (uint32_t)(bm + _row) * (uint32_t)ldA         \
                               + (uint32_t)((s) * BK + _seg * 8);              \
        const __half* _gb = Bb + (uint32_t)(bn + _row) * (uint32_t)ldB         \
                               + (uint32_t)((s) * BK + _seg * 8);              \
        asm volatile("cp.async.cg.shared.global [%0], [%1], 16;"               \
                     :: "r"(_base + _soff), "l"(_ga));                         \
        asm volatile("cp.async.cg.shared.global [%0], [%1], 16;"               \
                     :: "r"(_bB + _soff), "l"(_gb));                           \
    } while (0)

#define LOAD_STAGE(s) do {                                                     \
        LOAD_CHUNK(s, 0); LOAD_CHUNK(s, 1); LOAD_CHUNK(s, 2); LOAD_CHUNK(s, 3);\
        asm volatile("cp.async.commit_group;" ::: "memory");                   \
    } while (0)

    float acc[4][4][4];
    #pragma unroll
    for (int i = 0; i < 4; i++)
        #pragma unroll
        for (int j = 0; j < 4; j++)
            #pragma unroll
            for (int r = 0; r < 4; r++) acc[i][j][r] = 0.0f;

    LOAD_STAGE(0);
    LOAD_STAGE(1);

    for (int k0 = 0; k0 < KT; k0++) {
        if (k0 + 1 < KT) asm volatile("cp.async.wait_group 1;" ::: "memory");
        else             asm volatile("cp.async.wait_group 0;" ::: "memory");
        __syncthreads();

        const bool doLoad = (k0 + 2 < KT);
        const uint32_t stA = smem_base + (uint32_t)((k0 % NST) * STAGE_H * 2);
        const uint32_t stB = stA + (uint32_t)(TILE_H * 2);
        const uint32_t aRowAddr = stA + (uint32_t)(rowA * 128);
        const uint32_t bRowAddr = stB + (uint32_t)(rowB * 128);

        #pragma unroll
        for (int ks = 0; ks < BK / 16; ks++) {
            if (doLoad) {
                LOAD_CHUNK(k0 + 2, ks);
                if (ks == 3)
                    asm volatile("cp.async.commit_group;" ::: "memory");
            }

            const uint32_t offA = (uint32_t)(((2 * ks + selA) ^ xorv) << 4);
            const uint32_t offB = (uint32_t)(((2 * ks + selB) ^ xorv) << 4);
            uint32_t a[4][4], b[4][2];
            #pragma unroll
            for (int p = 0; p < 2; p++)
                LDMATRIX_X4(b[2 * p][0], b[2 * p][1], b[2 * p + 1][0], b[2 * p + 1][1],
                            bRowAddr + (uint32_t)(p * 16 * 128) + offB);
            #pragma unroll
            for (int mf = 0; mf < 4; mf++)
                LDMATRIX_X4(a[mf][0], a[mf][1], a[mf][2], a[mf][3],
                            aRowAddr + (uint32_t)(mf * 16 * 128) + offA);
            #pragma unroll
            for (int mf = 0; mf < 4; mf++)
                #pragma unroll
                for (int nf = 0; nf < 4; nf++)
                    asm volatile(
                        "mma.sync.aligned.m16n8k16.row.col.f32.f16.f16.f32 "
                        "{%0,%1,%2,%3}, {%4,%5,%6,%7}, {%8,%9}, {%0,%1,%2,%3};"
                        : "+f"(acc[mf][nf][0]), "+f"(acc[mf][nf][1]),
                          "+f"(acc[mf][nf][2]), "+f"(acc[mf][nf][3])
                        : "r"(a[mf][0]), "r"(a[mf][1]), "r"(a[mf][2]), "r"(a[mf][3]),
                          "r"(b[nf][0]), "r"(b[nf][1]));
        }
    }
#undef LOAD_STAGE
#undef LOAD_CHUNK

    // Epilogue
    const uint32_t mBase = (uint32_t)(bm + wm * 64 + g);
    const uint32_t nBase = (uint32_t)(bn + wn * 32 + 2 * tig);
    float psum[4][2];                       // per-mf row partials (rows g, g+8)
    #pragma unroll
    for (int mf = 0; mf < 4; mf++) { psum[mf][0] = 0.0f; psum[mf][1] = 0.0f; }

    #pragma unroll
    for (int mf = 0; mf < 4; mf++) {
        float ri0 = 1.0f, ri1 = 1.0f;
        if (!OUT_HALF && rowInv) {
            ri0 = rowInv[mBase + mf * 16];
            ri1 = rowInv[mBase + mf * 16 + 8];
        }
        #pragma unroll
        for (int nf = 0; nf < 4; nf++) {
            float v0 = acc[mf][nf][0] * alpha, v1 = acc[mf][nf][1] * alpha;
            float v2 = acc[mf][nf][2] * alpha, v3 = acc[mf][nf][3] * alpha;
            if (doExp) {
                v0 = __expf(v0); v1 = __expf(v1);
                v2 = __expf(v2); v3 = __expf(v3);
                psum[mf][0] += v0 + v1;
                psum[mf][1] += v2 + v3;
            }
            const uint32_t r0 = (mBase + mf * 16) * (uint32_t)ldC + nBase + nf * 8;
            const uint32_t r1 = r0 + 8 * (uint32_t)ldC;
            if (OUT_HALF) {
                __half* Ch = (__half*)Cb;
                *reinterpret_cast<__half2*>(&Ch[r0]) =
                    __float22half2_rn(make_float2(v0, v1));
                *reinterpret_cast<__half2*>(&Ch[r1]) =
                    __float22half2_rn(make_float2(v2, v3));
            } else {
                float* Cf = (float*)Cb;
                *reinterpret_cast<float2*>(&Cf[r0]) = make_float2(v0 * ri0, v1 * ri0);
                *reinterpret_cast<float2*>(&Cf[r1]) = make_float2(v2 * ri1, v3 * ri1);
            }
        }
    }

    // Row-partial emit (scores path only): quad reduce -> smem -> coalesced store.
    if (doExp && partBase) {
        #pragma unroll
        for (int mf = 0; mf < 4; mf++) {
            #pragma unroll
            for (int h = 0; h < 2; h++) {
                psum[mf][h] += __shfl_xor_sync(0xFFFFFFFFu, psum[mf][h], 1);
                psum[mf][h] += __shfl_xor_sync(0xFFFFFFFFu, psum[mf][h], 2);
            }
        }
        __syncthreads();                     // mainloop smem reads complete
        float* sp = reinterpret_cast<float*>(sm);   // [128 rows][4 wn]
        if (tig == 0) {
            #pragma unroll
            for (int mf = 0; mf < 4; mf++) {
                sp[(wm * 64 + mf * 16 + g)     * 4 + wn] = psum[mf][0];
                sp[(wm * 64 + mf * 16 + g + 8) * 4 + wn] = psum[mf][1];
            }
        }
        __syncthreads();
        if (tid < 128) {
            const float* r = sp + tid * 4;
            partBase[tid] = (r[0] + r[1]) + (r[2] + r[3]);
        }
    }
}

// ---------------------------------------------------------------------------
// Generic batched NT GEMM kernel. 32-bit element strides.
// ---------------------------------------------------------------------------
template <bool OUT_HALF>
__global__ __launch_bounds__(256, 2)
void gemm_h16_nt(const __half* __restrict__ A, const __half* __restrict__ B,
                 void* __restrict__ Cv, int K,
                 int ldA, int ldB, int ldC, float alpha,
                 uint32_t sA, uint32_t sB, uint32_t sC,
                 const float* __restrict__ rowInv, uint32_t sInv)
{
    const __half* Ab = A + (size_t)sA * blockIdx.z;
    const __half* Bb = B + (size_t)sB * blockIdx.z;
    void* Cb = (char*)Cv + (size_t)(OUT_HALF ? 2 : 4) * sC * blockIdx.z;
    const float* ri = rowInv ? rowInv + (size_t)sInv * blockIdx.z : nullptr;
    gemm_body<OUT_HALF>(Ab, Bb, Cb, K, ldA, ldB, ldC, alpha,
                        blockIdx.y * BM, blockIdx.x * BN, 0, ri, nullptr);
}

// ---------------------------------------------------------------------------
// Merged Vt + exp-scores kernel. grid (16, 24, NB):
//   y in [0,8):   V^T_b tile  (M=DH: y*128, N=SEQ: x*128)
//   y in [8,24):  exp-scores tile + row partials -> g_Part[x][z*SEQ + bm ..]
// ---------------------------------------------------------------------------
__global__ __launch_bounds__(256, 2)
void vt_scores_kernel(const __half* __restrict__ xh,
                      const __half* __restrict__ wv,
                      const __half* __restrict__ QK,
                      __half* __restrict__ Vt, __half* __restrict__ At,
                      float* __restrict__ part, float scale)
{
    const uint32_t z = blockIdx.z;
    const __half* A;  const __half* B;  __half* C;
    int K, ldA, ldB, ldC, bm, doExp;
    float alpha;
    float* pb;
    if (blockIdx.y < 8) {              // V^T_b = Wv @ x_b^T
        A = wv;
        B = xh + (size_t)z * (SEQ * DIN);
        C = Vt + (size_t)z * (DH * SEQ);
        K = DIN; ldA = DIN; ldB = DIN; ldC = SEQ;
        bm = blockIdx.y * BM;
        alpha = 1.0f; doExp = 0; pb = nullptr;
    } else {                            // exp-scores
        A = QK + (size_t)z * (SEQ * 2 * DH);
        B = A + DH;
        C = At + (size_t)z * (SEQ * SEQ);
        K = DH; ldA = 2 * DH; ldB = 2 * DH; ldC = SEQ;
        bm = (blockIdx.y - 8) * BM;
        alpha = scale; doExp = 1;
        pb = part + (size_t)blockIdx.x * (NB * SEQ) + z * SEQ + bm;
    }
    gemm_body<true>(A, B, C, K, ldA, ldB, ldC, alpha, bm, blockIdx.x * BN,
                    doExp, nullptr, pb);
}

// ---------------------------------------------------------------------------
// Reduce 16 partials per row -> reciprocal. 8192 rows, 32 blocks x 256 thr.
// part layout: [16][NB*SEQ] (coalesced reads).
// ---------------------------------------------------------------------------
__global__ __launch_bounds__(256)
void invreduce_kernel(const float* __restrict__ part, float* __restrict__ inv)
{
    const int r = blockIdx.x * 256 + threadIdx.x;     // 0..8191
    float s = 0.0f;
    #pragma unroll
    for (int t = 0; t < 16; t++)
        s += part[t * (NB * SEQ) + r];
    inv[r] = 1.0f / s;
}

// ---------------------------------------------------------------------------
// Fused fp32 -> fp16 convert for x, Wq, Wk, Wv in ONE launch.
// ---------------------------------------------------------------------------
__global__ __launch_bounds__(256)
void cvt_all_kernel(const float4* __restrict__ x,  uint4* __restrict__ xh,
                    const float4* __restrict__ wq, const float4* __restrict__ wk,
                    uint4* __restrict__ wqk,
                    const float4* __restrict__ wv, uint4* __restrict__ wvh)
{
    const int b = blockIdx.x;
    const float4* src;
    uint4* dst;
    int off;
    if (b < 4096)      { src = x;  dst = xh;  off = b; }
    else if (b < 4608) { src = wq; dst = wqk; off = b - 4096; }
    else if (b < 5120) { src = wk; dst = wqk + (size_t)(DH * DIN) / 8; off = b - 4608; }
    else               { src = wv; dst = wvh; off = b - 5120; }

    const int i = off * 256 + threadIdx.x;
    const float4 u = src[2 * i], v = src[2 * i + 1];
    __half2 h0 = __float22half2_rn(make_float2(u.x, u.y));
    __half2 h1 = __float22half2_rn(make_float2(u.z, u.w));
    __half2 h2 = __float22half2_rn(make_float2(v.x, v.y));
    __half2 h3 = __float22half2_rn(make_float2(v.z, v.w));
    uint4 o;
    o.x = *reinterpret_cast<uint32_t*>(&h0);
    o.y = *reinterpret_cast<uint32_t*>(&h1);
    o.z = *reinterpret_cast<uint32_t*>(&h2);
    o.w = *reinterpret_cast<uint32_t*>(&h3);
    dst[i] = o;
}

// ---------------------------------------------------------------------------
extern "C" void kernel_launch(void* const* d_in, const int* in_sizes, int n_in,
                              void* d_out, int out_size)
{
    (void)in_sizes; (void)n_in; (void)out_size;

    const float* x  = (const float*)d_in[0];
    const float* Wq = (const float*)d_in[1];
    const float* Wk = (const float*)d_in[2];
    const float* Wv = (const float*)d_in[3];
    float*       out = (float*)d_out;

    __half *xh, *wqk, *wv, *QK, *Vt, *At;
    float *part, *inv;
    cudaGetSymbolAddress((void**)&xh,   g_xh);
    cudaGetSymbolAddress((void**)&wqk,  g_Wqk);
    cudaGetSymbolAddress((void**)&wv,   g_Wv);
    cudaGetSymbolAddress((void**)&QK,   g_QK);
    cudaGetSymbolAddress((void**)&Vt,   g_Vt);
    cudaGetSymbolAddress((void**)&At,   g_At);
    cudaGetSymbolAddress((void**)&part, g_Part);
    cudaGetSymbolAddress((void**)&inv,  g_Inv);

    cudaFuncSetAttribute(gemm_h16_nt<true>,
                         cudaFuncAttributeMaxDynamicSharedMemorySize, SMEM_BYTES);
    cudaFuncSetAttribute(gemm_h16_nt<false>,
                         cudaFuncAttributeMaxDynamicSharedMemorySize, SMEM_BYTES);
    cudaFuncSetAttribute(vt_scores_kernel,
                         cudaFuncAttributeMaxDynamicSharedMemorySize, SMEM_BYTES);

    // 0) convert all inputs to fp16, one launch
    cvt_all_kernel<<<5632, 256>>>((const float4*)x,  (uint4*)xh,
                                  (const float4*)Wq, (const float4*)Wk,
                                  (uint4*)wqk,
                                  (const float4*)Wv, (uint4*)wv);

    // 1) [Q|K] = xh @ [Wq;Wk]^T : one GEMM, N = 2*DH, fp16 out
    {
        dim3 grid((2 * DH) / BN, (NB * SEQ) / BM, 1);     // (16, 64)
        gemm_h16_nt<true><<<grid, 256, SMEM_BYTES>>>(xh, wqk, QK, DIN,
                                                     DIN, DIN, 2 * DH, 1.0f,
                                                     0, 0, 0, nullptr, 0);
    }

    // 2) V^T AND exp-scores (+ row partials), one merged launch
    {
        const float scale = 1.0f / sqrtf((float)SEQ);
        dim3 grid(16, 24, NB);                            // 1536 CTAs
        vt_scores_kernel<<<grid, 256, SMEM_BYTES>>>(xh, wv, QK, Vt, At,
                                                    part, scale);
    }

    // 3) reduce 16 partials/row -> reciprocals (8192 rows)
    invreduce_kernel<<<32, 256>>>(part, inv);

    // 4) out_b = (expS_b @ (V^T_b)^T) * inv[row] : fp32 out
    {
        dim3 grid(DH / BN, SEQ / BM, NB);                 // (8, 16, 4)
        gemm_h16_nt<false><<<grid, 256, SMEM_BYTES>>>(At, Vt, out, SEQ,
                                                      SEQ, SEQ, DH, 1.0f,
                                                      (uint32_t)(SEQ * SEQ),
                                                      (uint32_t)(DH * SEQ),
                                                      (uint32_t)(SEQ * DH),
                                                      inv, (uint32_t)SEQ);
    }
}

// round 15
// speedup vs baseline: 1.0808x; 1.0007x over previous
#include <cuda_runtime.h>
#include <cuda_fp16.h>
#include <cstdint>
#include <math.h>

// Problem shape (fixed)
#define NB   4
#define SEQ  2048
#define DIN  1024
#define DH   1024

// ---------------------------------------------------------------------------
// Scratch (__device__ globals; no allocs allowed)
// ---------------------------------------------------------------------------
__device__ __half g_xh [(size_t)NB * SEQ * DIN];      // fp16 x            (16 MB)
__device__ __half g_Wqk[(size_t)2 * DH * DIN];        // [Wq; Wk] fp16     (4 MB)
__device__ __half g_Wv [(size_t)DH * DIN];            // fp16              (2 MB)
__device__ __half g_QK [(size_t)NB * SEQ * 2 * DH];   // [Q | K] fp16      (32 MB)
__device__ __half g_Vt [(size_t)NB * DH * SEQ];       // V^T fp16          (16 MB)
__device__ __half g_At [(size_t)NB * SEQ * SEQ];      // exp-scores fp16   (32 MB)
__device__ float  g_Part[(size_t)16 * NB * SEQ];      // row partials      (512 KB)

// ---------------------------------------------------------------------------
__device__ __forceinline__ uint32_t smem_u32(const void* p) {
    uint32_t a;
    asm("{ .reg .u64 t; cvta.to.shared.u64 t, %1; cvt.u32.u64 %0, t; }"
        : "=r"(a) : "l"(p));
    return a;
}

#define LDMATRIX_X4(r0, r1, r2, r3, addr)                                      \
    asm volatile("ldmatrix.sync.aligned.m8n8.x4.shared.b16 {%0,%1,%2,%3}, [%4];" \
                 : "=r"(r0), "=r"(r1), "=r"(r2), "=r"(r3) : "r"(addr))

// ---------------------------------------------------------------------------
// fp16 m16n8k16 NT GEMM body:  C = f(alpha * A @ B^T)
//   doExp: apply exp() in epilogue; partOut: emit 128 per-row partial sums.
//   partIn (fp32 out only): 16 partials/row at stride NB*SEQ; epilogue
//   computes 1/rowsum in smem and scales each output row (deferred softmax).
//   Tile 128x128x64, 8 warps (64x32 warp tile), 3-stage cp.async, XOR swizzle.
// ---------------------------------------------------------------------------
constexpr int BM = 128, BN = 128, BK = 64, NST = 3;
constexpr int TILE_H  = BM * BK;                 // 8192 halfs = 16 KB per operand
constexpr int STAGE_H = 2 * TILE_H;              // 32 KB per stage
constexpr int SMEM_BYTES = NST * STAGE_H * 2;    // 98304 B

template <bool OUT_HALF>
__device__ __forceinline__
void gemm_body(const __half* __restrict__ Ab, const __half* __restrict__ Bb,
               void* __restrict__ Cb, int K,
               int ldA, int ldB, int ldC, float alpha,
               int bm, int bn, int doExp,
               const float* __restrict__ partIn,
               float* __restrict__ partOut)
{
    extern __shared__ __align__(16) __half sm[];

    const int tid  = threadIdx.x;
    const int wid  = tid >> 5;
    const int lane = tid & 31;
    const int g    = lane >> 2;      // 0..7
    const int tig  = lane & 3;       // 0..3

    const int wm = wid >> 2;         // 0..1 : 64-row warp slab
    const int wn = wid & 3;          // 0..3 : 32-col warp slab
    const int KT = K / BK;

    const uint32_t smem_base = smem_u32(sm);

    // ldmatrix per-lane row/chunk precompute (row&7 == lane&7 for all bases).
    const int xorv = lane & 7;
    const int rowA = wm * 64 + (lane & 7) + ((lane >> 3) & 1) * 8;
    const int selA = lane >> 4;                   // 0:c0 1:c1
    const int rowB = wn * 32 + (lane & 7) + ((lane >> 4) & 1) * 8;
    const int selB = (lane >> 3) & 1;             // 0:c0 1:c1

#define LOAD_CHUNK(s, i) do {                                                  \
        const uint32_t _base = smem_base + (uint32_t)(((s) % NST) * STAGE_H * 2); \
        const uint32_t _bB   = _base + (uint32_t)(TILE_H * 2);                 \
        const int _idx = (i) * 256 + tid;                                      \
        const int _row = _idx >> 3;                                            \
        const int _seg = _idx & 7;                                             \
        const uint32_t _soff = (uint32_t)(_row * 128 +                         \
                               ((_seg ^ (_row & 7)) << 4));                    \
        const __half* _ga = Ab + (uint32_t)(bm + _row) * (uint32_t)ldA         \
                               + (uint32_t)((s) * BK + _seg * 8);              \
        const __half* _gb = Bb + (uint32_t)(bn + _row) * (uint32_t)ldB         \
                               + (uint32_t)((s) * BK + _seg * 8);              \
        asm volatile("cp.async.cg.shared.global [%0], [%1], 16;"               \
                     :: "r"(_base + _soff), "l"(_ga));                         \
        asm volatile("cp.async.cg.shared.global [%0], [%1], 16;"               \
                     :: "r"(_bB + _soff), "l"(_gb));                           \
    } while (0)

#define LOAD_STAGE(s) do {                                                     \
        LOAD_CHUNK(s, 0); LOAD_CHUNK(s, 1); LOAD_CHUNK(s, 2); LOAD_CHUNK(s, 3);\
        asm volatile("cp.async.commit_group;" ::: "memory");                   \
    } while (0)

    float acc[4][4][4];
    #pragma unroll
    for (int i = 0; i < 4; i++)
        #pragma unroll
        for (int j = 0; j < 4; j++)
            #pragma unroll
            for (int r = 0; r < 4; r++) acc[i][j][r] = 0.0f;

    LOAD_STAGE(0);
    LOAD_STAGE(1);

    for (int k0 = 0; k0 < KT; k0++) {
        if (k0 + 1 < KT) asm volatile("cp.async.wait_group 1;" ::: "memory");
        else             asm volatile("cp.async.wait_group 0;" ::: "memory");
        __syncthreads();

        const bool doLoad = (k0 + 2 < KT);
        const uint32_t stA = smem_base + (uint32_t)((k0 % NST) * STAGE_H * 2);
        const uint32_t stB = stA + (uint32_t)(TILE_H * 2);
        const uint32_t aRowAddr = stA + (uint32_t)(rowA * 128);
        const uint32_t bRowAddr = stB + (uint32_t)(rowB * 128);

        #pragma unroll
        for (int ks = 0; ks < BK / 16; ks++) {
            if (doLoad) {
                LOAD_CHUNK(k0 + 2, ks);
                if (ks == 3)
                    asm volatile("cp.async.commit_group;" ::: "memory");
            }

            const uint32_t offA = (uint32_t)(((2 * ks + selA) ^ xorv) << 4);
            const uint32_t offB = (uint32_t)(((2 * ks + selB) ^ xorv) << 4);
            uint32_t a[4][4], b[4][2];
            #pragma unroll
            for (int p = 0; p < 2; p++)
                LDMATRIX_X4(b[2 * p][0], b[2 * p][1], b[2 * p + 1][0], b[2 * p + 1][1],
                            bRowAddr + (uint32_t)(p * 16 * 128) + offB);
            #pragma unroll
            for (int mf = 0; mf < 4; mf++)
                LDMATRIX_X4(a[mf][0], a[mf][1], a[mf][2], a[mf][3],
                            aRowAddr + (uint32_t)(mf * 16 * 128) + offA);
            #pragma unroll
            for (int mf = 0; mf < 4; mf++)
                #pragma unroll
                for (int nf = 0; nf < 4; nf++)
                    asm volatile(
                        "mma.sync.aligned.m16n8k16.row.col.f32.f16.f16.f32 "
                        "{%0,%1,%2,%3}, {%4,%5,%6,%7}, {%8,%9}, {%0,%1,%2,%3};"
                        : "+f"(acc[mf][nf][0]), "+f"(acc[mf][nf][1]),
                          "+f"(acc[mf][nf][2]), "+f"(acc[mf][nf][3])
                        : "r"(a[mf][0]), "r"(a[mf][1]), "r"(a[mf][2]), "r"(a[mf][3]),
                          "r"(b[nf][0]), "r"(b[nf][1]));
        }
    }
#undef LOAD_STAGE
#undef LOAD_CHUNK

    // --- Deferred-normalization reciprocal table (fp32-out path only) ---
    float* sinv = reinterpret_cast<float*>(sm);      // 128 floats (stage smem idle)
    if (!OUT_HALF && partIn) {
        __syncthreads();                             // mainloop smem reads done
        if (tid < 128) {
            float s = 0.0f;
            #pragma unroll
            for (int t = 0; t < 16; t++)
                s += partIn[t * (NB * SEQ) + tid];   // partIn pre-offset to row bm
            sinv[tid] = 1.0f / s;
        }
        __syncthreads();
    }

    // Epilogue
    const uint32_t mBase = (uint32_t)(bm + wm * 64 + g);
    const uint32_t nBase = (uint32_t)(bn + wn * 32 + 2 * tig);
    float psum[4][2];
    #pragma unroll
    for (int mf = 0; mf < 4; mf++) { psum[mf][0] = 0.0f; psum[mf][1] = 0.0f; }

    #pragma unroll
    for (int mf = 0; mf < 4; mf++) {
        float ri0 = 1.0f, ri1 = 1.0f;
        if (!OUT_HALF && partIn) {
            ri0 = sinv[wm * 64 + mf * 16 + g];
            ri1 = sinv[wm * 64 + mf * 16 + g + 8];
        }
        #pragma unroll
        for (int nf = 0; nf < 4; nf++) {
            float v0 = acc[mf][nf][0] * alpha, v1 = acc[mf][nf][1] * alpha;
            float v2 = acc[mf][nf][2] * alpha, v3 = acc[mf][nf][3] * alpha;
            if (doExp) {
                v0 = __expf(v0); v1 = __expf(v1);
                v2 = __expf(v2); v3 = __expf(v3);
                psum[mf][0] += v0 + v1;
                psum[mf][1] += v2 + v3;
            }
            const uint32_t r0 = (mBase + mf * 16) * (uint32_t)ldC + nBase + nf * 8;
            const uint32_t r1 = r0 + 8 * (uint32_t)ldC;
            if (OUT_HALF) {
                __half* Ch = (__half*)Cb;
                *reinterpret_cast<__half2*>(&Ch[r0]) =
                    __float22half2_rn(make_float2(v0, v1));
                *reinterpret_cast<__half2*>(&Ch[r1]) =
                    __float22half2_rn(make_float2(v2, v3));
            } else {
                float* Cf = (float*)Cb;
                *reinterpret_cast<float2*>(&Cf[r0]) = make_float2(v0 * ri0, v1 * ri0);
                *reinterpret_cast<float2*>(&Cf[r1]) = make_float2(v2 * ri1, v3 * ri1);
            }
        }
    }

    // Row-partial emit (scores path only): quad reduce -> smem -> coalesced store.
    if (doExp && partOut) {
        #pragma unroll
        for (int mf = 0; mf < 4; mf++) {
            #pragma unroll
            for (int h = 0; h < 2; h++) {
                psum[mf][h] += __shfl_xor_sync(0xFFFFFFFFu, psum[mf][h], 1);
                psum[mf][h] += __shfl_xor_sync(0xFFFFFFFFu, psum[mf][h], 2);
            }
        }
        __syncthreads();                     // mainloop smem reads complete
        float* sp = reinterpret_cast<float*>(sm);   // [128 rows][4 wn]
        if (tig == 0) {
            #pragma unroll
            for (int mf = 0; mf < 4; mf++) {
                sp[(wm * 64 + mf * 16 + g)     * 4 + wn] = psum[mf][0];
                sp[(wm * 64 + mf * 16 + g + 8) * 4 + wn] = psum[mf][1];
            }
        }
        __syncthreads();
        if (tid < 128) {
            const float* r = sp + tid * 4;
            partOut[tid] = (r[0] + r[1]) + (r[2] + r[3]);
        }
    }
}

// ---------------------------------------------------------------------------
// Generic batched NT GEMM kernel. 32-bit element strides.
// partIn: 16 row partials per row ([16][NB*SEQ]); PV normalization.
// ---------------------------------------------------------------------------
template <bool OUT_HALF>
__global__ __launch_bounds__(256, 2)
void gemm_h16_nt(const __half* __restrict__ A, const __half* __restrict__ B,
                 void* __restrict__ Cv, int K,
                 int ldA, int ldB, int ldC, float alpha,
                 uint32_t sA, uint32_t sB, uint32_t sC,
                 const float* __restrict__ partIn)
{
    const __half* Ab = A + (size_t)sA * blockIdx.z;
    const __half* Bb = B + (size_t)sB * blockIdx.z;
    void* Cb = (char*)Cv + (size_t)(OUT_HALF ? 2 : 4) * sC * blockIdx.z;
    const float* pi = partIn
        ? partIn + (size_t)blockIdx.z * SEQ + blockIdx.y * BM : nullptr;
    gemm_body<OUT_HALF>(Ab, Bb, Cb, K, ldA, ldB, ldC, alpha,
                        blockIdx.y * BM, blockIdx.x * BN, 0, pi, nullptr);
}

// ---------------------------------------------------------------------------
// Merged Vt + exp-scores kernel. grid (16, 24, NB):
//   y in [0,8):   V^T_b tile  (M=DH: y*128, N=SEQ: x*128)
//   y in [8,24):  exp-scores tile + row partials -> g_Part[x][z*SEQ + bm ..]
// ---------------------------------------------------------------------------
__global__ __launch_bounds__(256, 2)
void vt_scores_kernel(const __half* __restrict__ xh,
                      const __half* __restrict__ wv,
                      const __half* __restrict__ QK,
                      __half* __restrict__ Vt, __half* __restrict__ At,
                      float* __restrict__ part, float scale)
{
    const uint32_t z = blockIdx.z;
    const __half* A;  const __half* B;  __half* C;
    int K, ldA, ldB, ldC, bm, doExp;
    float alpha;
    float* pb;
    if (blockIdx.y < 8) {              // V^T_b = Wv @ x_b^T
        A = wv;
        B = xh + (size_t)z * (SEQ * DIN);
        C = Vt + (size_t)z * (DH * SEQ);
        K = DIN; ldA = DIN; ldB = DIN; ldC = SEQ;
        bm = blockIdx.y * BM;
        alpha = 1.0f; doExp = 0; pb = nullptr;
    } else {                            // exp-scores
        A = QK + (size_t)z * (SEQ * 2 * DH);
        B = A + DH;
        C = At + (size_t)z * (SEQ * SEQ);
        K = DH; ldA = 2 * DH; ldB = 2 * DH; ldC = SEQ;
        bm = (blockIdx.y - 8) * BM;
        alpha = scale; doExp = 1;
        pb = part + (size_t)blockIdx.x * (NB * SEQ) + z * SEQ + bm;
    }
    gemm_body<true>(A, B, C, K, ldA, ldB, ldC, alpha, bm, blockIdx.x * BN,
                    doExp, nullptr, pb);
}

// ---------------------------------------------------------------------------
// Fused fp32 -> fp16 convert for x, Wq, Wk, Wv in ONE launch.
// ---------------------------------------------------------------------------
__global__ __launch_bounds__(256)
void cvt_all_kernel(const float4* __restrict__ x,  uint4* __restrict__ xh,
                    const float4* __restrict__ wq, const float4* __restrict__ wk,
                    uint4* __restrict__ wqk,
                    const float4* __restrict__ wv, uint4* __restrict__ wvh)
{
    const int b = blockIdx.x;
    const float4* src;
    uint4* dst;
    int off;
    if (b < 4096)      { src = x;  dst = xh;  off = b; }
    else if (b < 4608) { src = wq; dst = wqk; off = b - 4096; }
    else if (b < 5120) { src = wk; dst = wqk + (size_t)(DH * DIN) / 8; off = b - 4608; }
    else               { src = wv; dst = wvh; off = b - 5120; }

    const int i = off * 256 + threadIdx.x;
    const float4 u = src[2 * i], v = src[2 * i + 1];
    __half2 h0 = __float22half2_rn(make_float2(u.x, u.y));
    __half2 h1 = __float22half2_rn(make_float2(u.z, u.w));
    __half2 h2 = __float22half2_rn(make_float2(v.x, v.y));
    __half2 h3 = __float22half2_rn(make_float2(v.z, v.w));
    uint4 o;
    o.x = *reinterpret_cast<uint32_t*>(&h0);
    o.y = *reinterpret_cast<uint32_t*>(&h1);
    o.z = *reinterpret_cast<uint32_t*>(&h2);
    o.w = *reinterpret_cast<uint32_t*>(&h3);
    dst[i] = o;
}

// ---------------------------------------------------------------------------
extern "C" void kernel_launch(void* const* d_in, const int* in_sizes, int n_in,
                              void* d_out, int out_size)
{
    (void)in_sizes; (void)n_in; (void)out_size;

    const float* x  = (const float*)d_in[0];
    const float* Wq = (const float*)d_in[1];
    const float* Wk = (const float*)d_in[2];
    const float* Wv = (const float*)d_in[3];
    float*       out = (float*)d_out;

    __half *xh, *wqk, *wv, *QK, *Vt, *At;
    float *part;
    cudaGetSymbolAddress((void**)&xh,   g_xh);
    cudaGetSymbolAddress((void**)&wqk,  g_Wqk);
    cudaGetSymbolAddress((void**)&wv,   g_Wv);
    cudaGetSymbolAddress((void**)&QK,   g_QK);
    cudaGetSymbolAddress((void**)&Vt,   g_Vt);
    cudaGetSymbolAddress((void**)&At,   g_At);
    cudaGetSymbolAddress((void**)&part, g_Part);

    cudaFuncSetAttribute(gemm_h16_nt<true>,
                         cudaFuncAttributeMaxDynamicSharedMemorySize, SMEM_BYTES);
    cudaFuncSetAttribute(gemm_h16_nt<false>,
                         cudaFuncAttributeMaxDynamicSharedMemorySize, SMEM_BYTES);
    cudaFuncSetAttribute(vt_scores_kernel,
                         cudaFuncAttributeMaxDynamicSharedMemorySize, SMEM_BYTES);

    // 0) convert all inputs to fp16, one launch
    cvt_all_kernel<<<5632, 256>>>((const float4*)x,  (uint4*)xh,
                                  (const float4*)Wq, (const float4*)Wk,
                                  (uint4*)wqk,
                                  (const float4*)Wv, (uint4*)wv);

    // 1) [Q|K] = xh @ [Wq;Wk]^T : one GEMM, N = 2*DH, fp16 out
    {
        dim3 grid((2 * DH) / BN, (NB * SEQ) / BM, 1);     // (16, 64)
        gemm_h16_nt<true><<<grid, 256, SMEM_BYTES>>>(xh, wqk, QK, DIN,
                                                     DIN, DIN, 2 * DH, 1.0f,
                                                     0, 0, 0, nullptr);
    }

    // 2) V^T AND exp-scores (+ row partials), one merged launch
    {
        const float scale = 1.0f / sqrtf((float)SEQ);
        dim3 grid(16, 24, NB);                            // 1536 CTAs
        vt_scores_kernel<<<grid, 256, SMEM_BYTES>>>(xh, wv, QK, Vt, At,
                                                    part, scale);
    }

    // 3) out_b = (expS_b @ (V^T_b)^T) * (1/rowsum) : fp32 out
    //    reciprocals computed in-kernel from the 16 row partials.
    {
        dim3 grid(DH / BN, SEQ / BM, NB);                 // (8, 16, 4)
        gemm_h16_nt<false><<<grid, 256, SMEM_BYTES>>>(At, Vt, out, SEQ,
                                                      SEQ, SEQ, DH, 1.0f,
                                                      (uint32_t)(SEQ * SEQ),
                                                      (uint32_t)(DH * SEQ),
                                                      (uint32_t)(SEQ * DH),
                                                      part);
    }
}